// round 6
// baseline (speedup 1.0000x reference)
#include <cuda_runtime.h>
#include <math.h>

// ---------------- problem constants ----------------
#define BATCH 2
#define SEQ 2048
#define DMODEL 1024
#define NHEADS 16
#define HDIM 64
#define FFN 4096
#define NTOK (BATCH * SEQ)          // 4096 rows
#define QKVW (3 * DMODEL)           // 3072
#define LNEPS 1e-5f

// ---------------- scratch (static device memory; no allocations) ----------------
__device__ float g_qkv  [(size_t)NTOK * QKVW];                    // 50 MB
__device__ float g_scores[(size_t)BATCH * NHEADS * SEQ * SEQ];    // 536 MB
__device__ float g_vals [(size_t)NTOK * DMODEL];                  // 16 MB
__device__ float g_attn [(size_t)NTOK * DMODEL];
__device__ float g_h    [(size_t)NTOK * DMODEL];
__device__ float g_ffn1 [(size_t)NTOK * FFN];                     // 64 MB
__device__ float g_ffn2 [(size_t)NTOK * DMODEL];

// ---------------- warp reductions ----------------
__device__ __forceinline__ float warpMax(float v) {
    #pragma unroll
    for (int o = 16; o > 0; o >>= 1) v = fmaxf(v, __shfl_xor_sync(0xffffffffu, v, o));
    return v;
}
__device__ __forceinline__ float warpSum(float v) {
    #pragma unroll
    for (int o = 16; o > 0; o >>= 1) v += __shfl_xor_sync(0xffffffffu, v, o);
    return v;
}

// ---------------- generic tiled GEMM ----------------
// C[M,N] = alpha * A[M,K] @ op(B) (+ bias[n]) (+ relu) (+ res[row,col])
// TRANSB=false: B is [K,N] row-major (ldb).  TRANSB=true: B is [N,K] row-major (ldb), C = A@B^T.
// Batched over blockIdx.z; per-operand offset = (z/heads)*SO + (z%heads)*SH.
// EPI: 0=none, 1=+bias, 2=+bias,relu, 3=+bias,+res
template<int BM, int BN, int BK, int TM, int TN, bool TRANSB, int EPI>
__global__ void __launch_bounds__((BM/TM)*(BN/TN))
gemm_kernel(const float* __restrict__ A, const float* __restrict__ B,
            float* __restrict__ C, const float* __restrict__ bias,
            const float* __restrict__ res,
            int K, int lda, int ldb, int ldc, int ldres,
            float alpha, int heads,
            long long aSO, long long aSH, long long bSO, long long bSH,
            long long cSO, long long cSH)
{
    constexpr int NT = (BM/TM)*(BN/TN);
    __shared__ float As[BK][BM + 4];
    __shared__ float Bs[BK][BN + 4];

    const int tid = threadIdx.x;
    const int tx  = tid % (BN/TN);
    const int ty  = tid / (BN/TN);
    const int m0  = blockIdx.y * BM;
    const int n0  = blockIdx.x * BN;

    {
        const int zo = blockIdx.z / heads;
        const int zh = blockIdx.z % heads;
        A += zo * aSO + zh * aSH;
        B += zo * bSO + zh * bSH;
        C += zo * cSO + zh * cSH;
    }

    float acc[TM][TN];
    #pragma unroll
    for (int i = 0; i < TM; i++)
        #pragma unroll
        for (int j = 0; j < TN; j++) acc[i][j] = 0.0f;

    for (int k0 = 0; k0 < K; k0 += BK) {
        // load A tile [BM x BK] -> As[k][m] (transposed)
        #pragma unroll
        for (int idx = tid; idx < BM*BK/4; idx += NT) {
            const int r  = idx / (BK/4);
            const int c4 = idx % (BK/4);
            float4 v = *(const float4*)(A + (long long)(m0 + r) * lda + k0 + c4*4);
            As[c4*4+0][r] = v.x; As[c4*4+1][r] = v.y;
            As[c4*4+2][r] = v.z; As[c4*4+3][r] = v.w;
        }
        if (!TRANSB) {
            // B tile [BK x BN] -> Bs[k][n]
            #pragma unroll
            for (int idx = tid; idx < BK*BN/4; idx += NT) {
                const int r  = idx / (BN/4);
                const int c4 = idx % (BN/4);
                float4 v = *(const float4*)(B + (long long)(k0 + r) * ldb + n0 + c4*4);
                *(float4*)(&Bs[r][c4*4]) = v;
            }
        } else {
            // B tile [BN rows x BK cols] -> Bs[k][n] (transpose on store)
            #pragma unroll
            for (int idx = tid; idx < BN*BK/4; idx += NT) {
                const int r  = idx / (BK/4);
                const int c4 = idx % (BK/4);
                float4 v = *(const float4*)(B + (long long)(n0 + r) * ldb + k0 + c4*4);
                Bs[c4*4+0][r] = v.x; Bs[c4*4+1][r] = v.y;
                Bs[c4*4+2][r] = v.z; Bs[c4*4+3][r] = v.w;
            }
        }
        __syncthreads();

        #pragma unroll
        for (int kk = 0; kk < BK; kk++) {
            float a[TM], b[TN];
            #pragma unroll
            for (int i = 0; i < TM; i += 4)
                *(float4*)(a + i) = *(const float4*)(&As[kk][ty*TM + i]);
            #pragma unroll
            for (int j = 0; j < TN; j += 4)
                *(float4*)(b + j) = *(const float4*)(&Bs[kk][tx*TN + j]);
            #pragma unroll
            for (int i = 0; i < TM; i++)
                #pragma unroll
                for (int j = 0; j < TN; j++)
                    acc[i][j] = fmaf(a[i], b[j], acc[i][j]);
        }
        __syncthreads();
    }

    // epilogue
    #pragma unroll
    for (int i = 0; i < TM; i++) {
        const long long row = m0 + ty*TM + i;
        #pragma unroll
        for (int j = 0; j < TN; j++) {
            const int col = n0 + tx*TN + j;
            float v = acc[i][j] * alpha;
            if (EPI >= 1) v += bias[col];
            if (EPI == 2) v = fmaxf(v, 0.0f);
            if (EPI == 3) v += res[row * (long long)ldres + col];
            C[row * (long long)ldc + col] = v;
        }
    }
}

// ---------------- rowwise softmax over 2048 columns, in place ----------------
__global__ void __launch_bounds__(256) softmax_kernel(float* __restrict__ scores)
{
    __shared__ float sred[8];
    __shared__ float bc;
    const long long row = blockIdx.x;
    float* p = scores + row * (long long)SEQ;
    const int t = threadIdx.x;

    float v[8];
    float mx = -1e30f;
    #pragma unroll
    for (int i = 0; i < 8; i++) { v[i] = p[t + i*256]; mx = fmaxf(mx, v[i]); }

    mx = warpMax(mx);
    if ((t & 31) == 0) sred[t >> 5] = mx;
    __syncthreads();
    if (t < 32) {
        float x = (t < 8) ? sred[t] : -1e30f;
        x = warpMax(x);
        if (t == 0) bc = x;
    }
    __syncthreads();
    mx = bc;

    float sum = 0.0f;
    #pragma unroll
    for (int i = 0; i < 8; i++) { v[i] = expf(v[i] - mx); sum += v[i]; }

    sum = warpSum(sum);
    if ((t & 31) == 0) sred[t >> 5] = sum;
    __syncthreads();
    if (t < 32) {
        float x = (t < 8) ? sred[t] : 0.0f;
        x = warpSum(x);
        if (t == 0) bc = x;
    }
    __syncthreads();
    const float inv = 1.0f / bc;

    #pragma unroll
    for (int i = 0; i < 8; i++) p[t + i*256] = v[i] * inv;
}

// ---------------- LayerNorm over D=1024, one block (256 threads) per row ----------------
__global__ void __launch_bounds__(256)
ln_kernel(const float* __restrict__ in, const float* __restrict__ gamma,
          const float* __restrict__ beta, float* __restrict__ out)
{
    __shared__ float sred[8];
    __shared__ float bc;
    const long long row = blockIdx.x;
    const int t = threadIdx.x;

    float4 v = *(const float4*)(in + row * (long long)DMODEL + t*4);
    float s = v.x + v.y + v.z + v.w;

    s = warpSum(s);
    if ((t & 31) == 0) sred[t >> 5] = s;
    __syncthreads();
    if (t < 32) {
        float x = (t < 8) ? sred[t] : 0.0f;
        x = warpSum(x);
        if (t == 0) bc = x;
    }
    __syncthreads();
    const float mean = bc * (1.0f / DMODEL);

    const float d0 = v.x - mean, d1 = v.y - mean, d2 = v.z - mean, d3 = v.w - mean;
    float sq = d0*d0 + d1*d1 + d2*d2 + d3*d3;

    sq = warpSum(sq);
    if ((t & 31) == 0) sred[t >> 5] = sq;
    __syncthreads();
    if (t < 32) {
        float x = (t < 8) ? sred[t] : 0.0f;
        x = warpSum(x);
        if (t == 0) bc = x;
    }
    __syncthreads();
    const float var = bc * (1.0f / DMODEL);
    const float inv = rsqrtf(var + LNEPS);

    float4 gv = *(const float4*)(gamma + t*4);
    float4 bv = *(const float4*)(beta  + t*4);
    float4 o;
    o.x = gv.x * d0 * inv + bv.x;
    o.y = gv.y * d1 * inv + bv.y;
    o.z = gv.z * d2 * inv + bv.z;
    o.w = gv.w * d3 * inv + bv.w;
    *(float4*)(out + row * (long long)DMODEL + t*4) = o;
}

// ---------------- launch ----------------
extern "C" void kernel_launch(void* const* d_in, const int* in_sizes, int n_in,
                              void* d_out, int out_size)
{
    const float* x      = (const float*)d_in[0];
    const float* W_qkv  = (const float*)d_in[1];
    const float* b_qkv  = (const float*)d_in[2];
    const float* W_o    = (const float*)d_in[3];
    const float* b_o    = (const float*)d_in[4];
    const float* gamma1 = (const float*)d_in[5];
    const float* beta1  = (const float*)d_in[6];
    const float* W1     = (const float*)d_in[7];
    const float* b1     = (const float*)d_in[8];
    const float* W2     = (const float*)d_in[9];
    const float* b2     = (const float*)d_in[10];
    const float* gamma2 = (const float*)d_in[11];
    const float* beta2  = (const float*)d_in[12];
    float* out = (float*)d_out;

    float *qkv, *scores, *vals, *attn, *hbuf, *f1, *f2;
    cudaGetSymbolAddress((void**)&qkv,    g_qkv);
    cudaGetSymbolAddress((void**)&scores, g_scores);
    cudaGetSymbolAddress((void**)&vals,   g_vals);
    cudaGetSymbolAddress((void**)&attn,   g_attn);
    cudaGetSymbolAddress((void**)&hbuf,   g_h);
    cudaGetSymbolAddress((void**)&f1,     g_ffn1);
    cudaGetSymbolAddress((void**)&f2,     g_ffn2);

    const dim3 blk(256);
    const long long qkvRowB = (long long)SEQ * QKVW;      // per-batch stride in qkv buffer
    const long long scB  = (long long)NHEADS * SEQ * SEQ; // per-batch stride in scores
    const long long scH  = (long long)SEQ * SEQ;          // per-head stride in scores

    // 1) qkv = x @ W_qkv + b_qkv      [4096 x 3072]
    gemm_kernel<128,128,16,8,8,false,1><<<dim3(QKVW/128, NTOK/128, 1), blk>>>(
        x, W_qkv, qkv, b_qkv, nullptr,
        DMODEL, DMODEL, QKVW, QKVW, 0, 1.0f, 1, 0,0,0,0,0,0);

    // 2) scores = 0.125 * Q @ K^T    batched over (b,h): 32 x [2048 x 2048], K=64
    gemm_kernel<128,128,16,8,8,true,0><<<dim3(SEQ/128, SEQ/128, BATCH*NHEADS), blk>>>(
        qkv /*Q at col h*192*/, qkv + HDIM /*K at col h*192+64*/, scores, nullptr, nullptr,
        HDIM, QKVW, QKVW, SEQ, 0, 0.125f, NHEADS,
        qkvRowB, 3*HDIM, qkvRowB, 3*HDIM, scB, scH);

    // 3) row softmax in place (65536 rows of 2048)
    softmax_kernel<<<BATCH*NHEADS*SEQ, blk>>>(scores);

    // 4) vals = P @ V  batched: 32 x [2048 x 64], K=2048 ; write to [b,s,h*64+d] layout
    gemm_kernel<128,64,16,8,4,false,0><<<dim3(1, SEQ/128, BATCH*NHEADS), blk>>>(
        scores, qkv + 2*HDIM /*V*/, vals, nullptr, nullptr,
        SEQ, SEQ, QKVW, DMODEL, 0, 1.0f, NHEADS,
        scB, scH, qkvRowB, 3*HDIM, (long long)SEQ*DMODEL, HDIM);

    // 5) attn = vals @ W_o + b_o + x (residual)   [4096 x 1024]
    gemm_kernel<128,128,16,8,8,false,3><<<dim3(DMODEL/128, NTOK/128, 1), blk>>>(
        vals, W_o, attn, b_o, x,
        DMODEL, DMODEL, DMODEL, DMODEL, DMODEL, 1.0f, 1, 0,0,0,0,0,0);

    // 6) h = LN1(attn)
    ln_kernel<<<NTOK, blk>>>(attn, gamma1, beta1, hbuf);

    // 7) f1 = relu(h @ W1 + b1)      [4096 x 4096]
    gemm_kernel<128,128,16,8,8,false,2><<<dim3(FFN/128, NTOK/128, 1), blk>>>(
        hbuf, W1, f1, b1, nullptr,
        DMODEL, DMODEL, FFN, FFN, 0, 1.0f, 1, 0,0,0,0,0,0);

    // 8) f2 = f1 @ W2 + b2 + h (residual)  [4096 x 1024]
    gemm_kernel<128,128,16,8,8,false,3><<<dim3(DMODEL/128, NTOK/128, 1), blk>>>(
        f1, W2, f2, b2, hbuf,
        FFN, FFN, DMODEL, DMODEL, DMODEL, 1.0f, 1, 0,0,0,0,0,0);

    // 9) out = LN2(f2)
    ln_kernel<<<NTOK, blk>>>(f2, gamma2, beta2, out);
}

// round 7
// speedup vs baseline: 1.0018x; 1.0018x over previous
#include <cuda_runtime.h>
#include <math.h>

// ---------------- problem constants ----------------
#define BATCH 2
#define SEQ 2048
#define DMODEL 1024
#define NHEADS 16
#define HDIM 64
#define FFN 4096
#define NTOK (BATCH * SEQ)          // 4096 rows
#define QKVW (3 * DMODEL)           // 3072
#define LNEPS 1e-5f

// ---------------- scratch (static device memory; no allocations) ----------------
__device__ float g_qkv  [(size_t)NTOK * QKVW];                    // 50 MB
__device__ float g_scores[(size_t)BATCH * NHEADS * SEQ * SEQ];    // 536 MB
__device__ float g_vals [(size_t)NTOK * DMODEL];                  // 16 MB
__device__ float g_attn [(size_t)NTOK * DMODEL];
__device__ float g_h    [(size_t)NTOK * DMODEL];
__device__ float g_ffn1 [(size_t)NTOK * FFN];                     // 64 MB
__device__ float g_ffn2 [(size_t)NTOK * DMODEL];

// ---------------- warp reductions ----------------
__device__ __forceinline__ float warpMax(float v) {
    #pragma unroll
    for (int o = 16; o > 0; o >>= 1) v = fmaxf(v, __shfl_xor_sync(0xffffffffu, v, o));
    return v;
}
__device__ __forceinline__ float warpSum(float v) {
    #pragma unroll
    for (int o = 16; o > 0; o >>= 1) v += __shfl_xor_sync(0xffffffffu, v, o);
    return v;
}

// ---------------- generic tiled GEMM ----------------
// C[M,N] = alpha * A[M,K] @ op(B) (+ bias[n]) (+ relu) (+ res[row,col])
// TRANSB=false: B is [K,N] row-major (ldb).  TRANSB=true: B is [N,K] row-major (ldb), C = A@B^T.
// Batched over blockIdx.z; per-operand offset = (z/heads)*SO + (z%heads)*SH.
// EPI: 0=none, 1=+bias, 2=+bias,relu, 3=+bias,+res
template<int BM, int BN, int BK, int TM, int TN, bool TRANSB, int EPI>
__global__ void __launch_bounds__((BM/TM)*(BN/TN))
gemm_kernel(const float* __restrict__ A, const float* __restrict__ B,
            float* __restrict__ C, const float* __restrict__ bias,
            const float* __restrict__ res,
            int K, int lda, int ldb, int ldc, int ldres,
            float alpha, int heads,
            long long aSO, long long aSH, long long bSO, long long bSH,
            long long cSO, long long cSH)
{
    constexpr int NT = (BM/TM)*(BN/TN);
    __shared__ float As[BK][BM + 4];
    __shared__ float Bs[BK][BN + 4];

    const int tid = threadIdx.x;
    const int tx  = tid % (BN/TN);
    const int ty  = tid / (BN/TN);
    const int m0  = blockIdx.y * BM;
    const int n0  = blockIdx.x * BN;

    {
        const int zo = blockIdx.z / heads;
        const int zh = blockIdx.z % heads;
        A += zo * aSO + zh * aSH;
        B += zo * bSO + zh * bSH;
        C += zo * cSO + zh * cSH;
    }

    float acc[TM][TN];
    #pragma unroll
    for (int i = 0; i < TM; i++)
        #pragma unroll
        for (int j = 0; j < TN; j++) acc[i][j] = 0.0f;

    for (int k0 = 0; k0 < K; k0 += BK) {
        // load A tile [BM x BK] -> As[k][m] (transposed)
        #pragma unroll
        for (int idx = tid; idx < BM*BK/4; idx += NT) {
            const int r  = idx / (BK/4);
            const int c4 = idx % (BK/4);
            float4 v = *(const float4*)(A + (long long)(m0 + r) * lda + k0 + c4*4);
            As[c4*4+0][r] = v.x; As[c4*4+1][r] = v.y;
            As[c4*4+2][r] = v.z; As[c4*4+3][r] = v.w;
        }
        if (!TRANSB) {
            // B tile [BK x BN] -> Bs[k][n]
            #pragma unroll
            for (int idx = tid; idx < BK*BN/4; idx += NT) {
                const int r  = idx / (BN/4);
                const int c4 = idx % (BN/4);
                float4 v = *(const float4*)(B + (long long)(k0 + r) * ldb + n0 + c4*4);
                *(float4*)(&Bs[r][c4*4]) = v;
            }
        } else {
            // B tile [BN rows x BK cols] -> Bs[k][n] (transpose on store)
            #pragma unroll
            for (int idx = tid; idx < BN*BK/4; idx += NT) {
                const int r  = idx / (BK/4);
                const int c4 = idx % (BK/4);
                float4 v = *(const float4*)(B + (long long)(n0 + r) * ldb + k0 + c4*4);
                Bs[c4*4+0][r] = v.x; Bs[c4*4+1][r] = v.y;
                Bs[c4*4+2][r] = v.z; Bs[c4*4+3][r] = v.w;
            }
        }
        __syncthreads();

        #pragma unroll
        for (int kk = 0; kk < BK; kk++) {
            float a[TM], b[TN];
            #pragma unroll
            for (int i = 0; i < TM; i += 4)
                *(float4*)(a + i) = *(const float4*)(&As[kk][ty*TM + i]);
            #pragma unroll
            for (int j = 0; j < TN; j += 4)
                *(float4*)(b + j) = *(const float4*)(&Bs[kk][tx*TN + j]);
            #pragma unroll
            for (int i = 0; i < TM; i++)
                #pragma unroll
                for (int j = 0; j < TN; j++)
                    acc[i][j] = fmaf(a[i], b[j], acc[i][j]);
        }
        __syncthreads();
    }

    // epilogue
    #pragma unroll
    for (int i = 0; i < TM; i++) {
        const long long row = m0 + ty*TM + i;
        #pragma unroll
        for (int j = 0; j < TN; j++) {
            const int col = n0 + tx*TN + j;
            float v = acc[i][j] * alpha;
            if (EPI >= 1) v += bias[col];
            if (EPI == 2) v = fmaxf(v, 0.0f);
            if (EPI == 3) v += res[row * (long long)ldres + col];
            C[row * (long long)ldc + col] = v;
        }
    }
}

// ---------------- rowwise softmax over 2048 columns, in place ----------------
__global__ void __launch_bounds__(256) softmax_kernel(float* __restrict__ scores)
{
    __shared__ float sred[8];
    __shared__ float bc;
    const long long row = blockIdx.x;
    float* p = scores + row * (long long)SEQ;
    const int t = threadIdx.x;

    float v[8];
    float mx = -1e30f;
    #pragma unroll
    for (int i = 0; i < 8; i++) { v[i] = p[t + i*256]; mx = fmaxf(mx, v[i]); }

    mx = warpMax(mx);
    if ((t & 31) == 0) sred[t >> 5] = mx;
    __syncthreads();
    if (t < 32) {
        float x = (t < 8) ? sred[t] : -1e30f;
        x = warpMax(x);
        if (t == 0) bc = x;
    }
    __syncthreads();
    mx = bc;

    float sum = 0.0f;
    #pragma unroll
    for (int i = 0; i < 8; i++) { v[i] = expf(v[i] - mx); sum += v[i]; }

    sum = warpSum(sum);
    if ((t & 31) == 0) sred[t >> 5] = sum;
    __syncthreads();
    if (t < 32) {
        float x = (t < 8) ? sred[t] : 0.0f;
        x = warpSum(x);
        if (t == 0) bc = x;
    }
    __syncthreads();
    const float inv = 1.0f / bc;

    #pragma unroll
    for (int i = 0; i < 8; i++) p[t + i*256] = v[i] * inv;
}

// ---------------- LayerNorm over D=1024, one block (256 threads) per row ----------------
__global__ void __launch_bounds__(256)
ln_kernel(const float* __restrict__ in, const float* __restrict__ gamma,
          const float* __restrict__ beta, float* __restrict__ out)
{
    __shared__ float sred[8];
    __shared__ float bc;
    const long long row = blockIdx.x;
    const int t = threadIdx.x;

    float4 v = *(const float4*)(in + row * (long long)DMODEL + t*4);
    float s = v.x + v.y + v.z + v.w;

    s = warpSum(s);
    if ((t & 31) == 0) sred[t >> 5] = s;
    __syncthreads();
    if (t < 32) {
        float x = (t < 8) ? sred[t] : 0.0f;
        x = warpSum(x);
        if (t == 0) bc = x;
    }
    __syncthreads();
    const float mean = bc * (1.0f / DMODEL);

    const float d0 = v.x - mean, d1 = v.y - mean, d2 = v.z - mean, d3 = v.w - mean;
    float sq = d0*d0 + d1*d1 + d2*d2 + d3*d3;

    sq = warpSum(sq);
    if ((t & 31) == 0) sred[t >> 5] = sq;
    __syncthreads();
    if (t < 32) {
        float x = (t < 8) ? sred[t] : 0.0f;
        x = warpSum(x);
        if (t == 0) bc = x;
    }
    __syncthreads();
    const float var = bc * (1.0f / DMODEL);
    const float inv = rsqrtf(var + LNEPS);

    float4 gv = *(const float4*)(gamma + t*4);
    float4 bv = *(const float4*)(beta  + t*4);
    float4 o;
    o.x = gv.x * d0 * inv + bv.x;
    o.y = gv.y * d1 * inv + bv.y;
    o.z = gv.z * d2 * inv + bv.z;
    o.w = gv.w * d3 * inv + bv.w;
    *(float4*)(out + row * (long long)DMODEL + t*4) = o;
}

// ---------------- launch ----------------
extern "C" void kernel_launch(void* const* d_in, const int* in_sizes, int n_in,
                              void* d_out, int out_size)
{
    const float* x      = (const float*)d_in[0];
    const float* W_qkv  = (const float*)d_in[1];
    const float* b_qkv  = (const float*)d_in[2];
    const float* W_o    = (const float*)d_in[3];
    const float* b_o    = (const float*)d_in[4];
    const float* gamma1 = (const float*)d_in[5];
    const float* beta1  = (const float*)d_in[6];
    const float* W1     = (const float*)d_in[7];
    const float* b1     = (const float*)d_in[8];
    const float* W2     = (const float*)d_in[9];
    const float* b2     = (const float*)d_in[10];
    const float* gamma2 = (const float*)d_in[11];
    const float* beta2  = (const float*)d_in[12];
    float* out = (float*)d_out;

    float *qkv, *scores, *vals, *attn, *hbuf, *f1, *f2;
    cudaGetSymbolAddress((void**)&qkv,    g_qkv);
    cudaGetSymbolAddress((void**)&scores, g_scores);
    cudaGetSymbolAddress((void**)&vals,   g_vals);
    cudaGetSymbolAddress((void**)&attn,   g_attn);
    cudaGetSymbolAddress((void**)&hbuf,   g_h);
    cudaGetSymbolAddress((void**)&f1,     g_ffn1);
    cudaGetSymbolAddress((void**)&f2,     g_ffn2);

    const dim3 blk(256);
    const long long qkvRowB = (long long)SEQ * QKVW;      // per-batch stride in qkv buffer
    const long long scB  = (long long)NHEADS * SEQ * SEQ; // per-batch stride in scores
    const long long scH  = (long long)SEQ * SEQ;          // per-head stride in scores

    // 1) qkv = x @ W_qkv + b_qkv      [4096 x 3072]
    gemm_kernel<128,128,16,8,8,false,1><<<dim3(QKVW/128, NTOK/128, 1), blk>>>(
        x, W_qkv, qkv, b_qkv, nullptr,
        DMODEL, DMODEL, QKVW, QKVW, 0, 1.0f, 1, 0,0,0,0,0,0);

    // 2) scores = 0.125 * Q @ K^T    batched over (b,h): 32 x [2048 x 2048], K=64
    gemm_kernel<128,128,16,8,8,true,0><<<dim3(SEQ/128, SEQ/128, BATCH*NHEADS), blk>>>(
        qkv /*Q at col h*192*/, qkv + HDIM /*K at col h*192+64*/, scores, nullptr, nullptr,
        HDIM, QKVW, QKVW, SEQ, 0, 0.125f, NHEADS,
        qkvRowB, 3*HDIM, qkvRowB, 3*HDIM, scB, scH);

    // 3) row softmax in place (65536 rows of 2048)
    softmax_kernel<<<BATCH*NHEADS*SEQ, blk>>>(scores);

    // 4) vals = P @ V  batched: 32 x [2048 x 64], K=2048 ; write to [b,s,h*64+d] layout
    gemm_kernel<128,64,16,8,4,false,0><<<dim3(1, SEQ/128, BATCH*NHEADS), blk>>>(
        scores, qkv + 2*HDIM /*V*/, vals, nullptr, nullptr,
        SEQ, SEQ, QKVW, DMODEL, 0, 1.0f, NHEADS,
        scB, scH, qkvRowB, 3*HDIM, (long long)SEQ*DMODEL, HDIM);

    // 5) attn = vals @ W_o + b_o + x (residual)   [4096 x 1024]
    gemm_kernel<128,128,16,8,8,false,3><<<dim3(DMODEL/128, NTOK/128, 1), blk>>>(
        vals, W_o, attn, b_o, x,
        DMODEL, DMODEL, DMODEL, DMODEL, DMODEL, 1.0f, 1, 0,0,0,0,0,0);

    // 6) h = LN1(attn)
    ln_kernel<<<NTOK, blk>>>(attn, gamma1, beta1, hbuf);

    // 7) f1 = relu(h @ W1 + b1)      [4096 x 4096]
    gemm_kernel<128,128,16,8,8,false,2><<<dim3(FFN/128, NTOK/128, 1), blk>>>(
        hbuf, W1, f1, b1, nullptr,
        DMODEL, DMODEL, FFN, FFN, 0, 1.0f, 1, 0,0,0,0,0,0);

    // 8) f2 = f1 @ W2 + b2 + h (residual)  [4096 x 1024]
    gemm_kernel<128,128,16,8,8,false,3><<<dim3(DMODEL/128, NTOK/128, 1), blk>>>(
        f1, W2, f2, b2, hbuf,
        FFN, FFN, DMODEL, DMODEL, DMODEL, 1.0f, 1, 0,0,0,0,0,0);

    // 9) out = LN2(f2)
    ln_kernel<<<NTOK, blk>>>(f2, gamma2, beta2, out);
}

// round 13
// speedup vs baseline: 2.1830x; 2.1791x over previous
#include <cuda_runtime.h>
#include <cuda_bf16.h>
#include <math.h>
#include <stdint.h>

#define BATCH 2
#define SEQ 2048
#define DMODEL 1024
#define NHEADS 16
#define HDIM 64
#define FFN 4096
#define NTOK (BATCH * SEQ)
#define QKVW (3 * DMODEL)
#define LNEPS 1e-5f

typedef __nv_bfloat16 bf16;
typedef __nv_bfloat162 bf162;

// ---------------- static device scratch ----------------
__device__ float g_scores[(size_t)BATCH * NHEADS * SEQ * SEQ];
__device__ float g_attn[(size_t)NTOK * DMODEL];
__device__ float g_hf[(size_t)NTOK * DMODEL];
__device__ float g_f2[(size_t)NTOK * DMODEL];
__device__ bf16 g_xh[(size_t)NTOK * DMODEL], g_xl[(size_t)NTOK * DMODEL];
__device__ bf16 g_WqT_h[(size_t)QKVW * DMODEL], g_WqT_l[(size_t)QKVW * DMODEL];
__device__ bf16 g_WoT_h[(size_t)DMODEL * DMODEL], g_WoT_l[(size_t)DMODEL * DMODEL];
__device__ bf16 g_W1T_h[(size_t)FFN * DMODEL], g_W1T_l[(size_t)FFN * DMODEL];
__device__ bf16 g_W2T_h[(size_t)DMODEL * FFN], g_W2T_l[(size_t)DMODEL * FFN];
__device__ bf16 g_qkv_h[(size_t)NTOK * QKVW], g_qkv_l[(size_t)NTOK * QKVW];
__device__ bf16 g_Vt_h[(size_t)BATCH * NHEADS * HDIM * SEQ], g_Vt_l[(size_t)BATCH * NHEADS * HDIM * SEQ];
__device__ bf16 g_P_h[(size_t)BATCH * NHEADS * SEQ * SEQ];
__device__ bf16 g_P_l[(size_t)BATCH * NHEADS * SEQ * SEQ];
__device__ bf16 g_vals_h[(size_t)NTOK * DMODEL], g_vals_l[(size_t)NTOK * DMODEL];
__device__ bf16 g_h_h[(size_t)NTOK * DMODEL], g_h_l[(size_t)NTOK * DMODEL];
__device__ bf16 g_f1_h[(size_t)NTOK * FFN], g_f1_l[(size_t)NTOK * FFN];

// ---------------- helpers ----------------
__device__ __forceinline__ float warpMax(float v) {
    #pragma unroll
    for (int o = 16; o > 0; o >>= 1) v = fmaxf(v, __shfl_xor_sync(0xffffffffu, v, o));
    return v;
}
__device__ __forceinline__ float warpSum(float v) {
    #pragma unroll
    for (int o = 16; o > 0; o >>= 1) v += __shfl_xor_sync(0xffffffffu, v, o);
    return v;
}
__device__ __forceinline__ void bsplit(float v, bf16& h, bf16& l) {
    h = __float2bfloat16(v);
    l = __float2bfloat16(v - __bfloat162float(h));
}

// ---------------- portable tensor-core primitives (base sm_103: NO tcgen05) ----------------
__device__ __forceinline__ void ldsm4(uint32_t* r, uint32_t a) {
    asm volatile("ldmatrix.sync.aligned.m8n8.x4.shared.b16 {%0,%1,%2,%3}, [%4];"
                 : "=r"(r[0]), "=r"(r[1]), "=r"(r[2]), "=r"(r[3]) : "r"(a));
}
__device__ __forceinline__ void mma16816(float* c, const uint32_t* a, const uint32_t* b) {
    asm volatile("mma.sync.aligned.m16n8k16.row.col.f32.bf16.bf16.f32 "
                 "{%0,%1,%2,%3}, {%4,%5,%6,%7}, {%8,%9}, {%0,%1,%2,%3};"
                 : "+f"(c[0]), "+f"(c[1]), "+f"(c[2]), "+f"(c[3])
                 : "r"(a[0]), "r"(a[1]), "r"(a[2]), "r"(a[3]), "r"(b[0]), "r"(b[1]));
}
__device__ __forceinline__ void cpasync16(uint32_t dst, const void* src) {
    asm volatile("cp.async.cg.shared.global [%0], [%1], 16;" :: "r"(dst), "l"(src));
}
#define CP_COMMIT() asm volatile("cp.async.commit_group;" ::: "memory")
#define CP_WAIT0()  asm volatile("cp.async.wait_group 0;" ::: "memory")
#define CP_WAIT1()  asm volatile("cp.async.wait_group 1;" ::: "memory")

// copy R x 32 bf16 tile (row stride ld elems, col offset k0) -> smem rows of 80B
template<int R>
__device__ __forceinline__ void cp_tile(const bf16* __restrict__ g, long long ld, int k0, uint32_t s)
{
    #pragma unroll
    for (int it = 0; it < R / 64; it++) {
        int idx = threadIdx.x + it * 256;
        int r = idx >> 2, c = idx & 3;
        cpasync16(s + r * 80 + c * 16, g + (long long)r * ld + k0 + c * 8);
    }
}

// =====================================================================
// mma.sync split-bf16 GEMM: C = alpha*(Ah+Al)[M,K] @ ((Bh+Bl)[N,K])^T
// BM=128, BK=32; 256 thr = 8 warps (4M x 2N), warp tile 32 x BN/2.
// EPI: 0 none, 1 +bias, 2 +bias+relu, 3 +bias+res
// =====================================================================
template<int BN, int EPI, bool WF32, bool WBF16>
__global__ void __launch_bounds__(256)
mm_gemm(const bf16* __restrict__ Ah, const bf16* __restrict__ Al,
        const bf16* __restrict__ Bh, const bf16* __restrict__ Bl,
        float* __restrict__ C, bf16* __restrict__ Ch, bf16* __restrict__ Cl,
        const float* __restrict__ bias, const float* __restrict__ res,
        int K, long long lda, long long ldb, long long ldc, long long ldres,
        float alpha, int heads,
        long long aSO, long long aSH, long long bSO, long long bSH,
        long long cSO, long long cSH)
{
    constexpr int SS  = 20480 + 2 * BN * 80;   // bytes per stage
    constexpr int NTL = BN / 16;               // n-tiles (8 wide) per warp
    constexpr int NP  = BN / 32;               // ldmatrix n-pairs per warp

    extern __shared__ char sm[];
    const uint32_t sb = (uint32_t)__cvta_generic_to_shared(sm);

    const int tid = threadIdx.x, lane = tid & 31, wid = tid >> 5;
    const int wm = wid >> 1, wn = wid & 1;
    const int m0 = blockIdx.y * 128, n0 = blockIdx.x * BN;
    const int zo = blockIdx.z / heads, zh = blockIdx.z % heads;

    const bf16* pAh = Ah + zo * aSO + zh * aSH + (long long)m0 * lda;
    const bf16* pAl = Al + zo * aSO + zh * aSH + (long long)m0 * lda;
    const bf16* pBh = Bh + zo * bSO + zh * bSH + (long long)n0 * ldb;
    const bf16* pBl = Bl + zo * bSO + zh * bSH + (long long)n0 * ldb;

    float acc[2][NTL][4];
    #pragma unroll
    for (int i = 0; i < 2; i++)
        #pragma unroll
        for (int j = 0; j < NTL; j++)
            #pragma unroll
            for (int c = 0; c < 4; c++) acc[i][j][c] = 0.0f;

    const int nck = K >> 5;

    // stage 0
    {
        uint32_t s = sb;
        cp_tile<128>(pAh, lda, 0, s);
        cp_tile<128>(pAl, lda, 0, s + 10240);
        cp_tile<BN >(pBh, ldb, 0, s + 20480);
        cp_tile<BN >(pBl, ldb, 0, s + 20480 + BN * 80);
    }
    CP_COMMIT();

    const uint32_t aRow  = (uint32_t)(wm * 32 + (lane & 15));
    const uint32_t aColB = (uint32_t)((lane >> 4) * 16);
    const uint32_t bRow  = (uint32_t)(wn * (BN / 2) + (lane & 15));

    for (int i = 0; i < nck; i++) {
        if (i + 1 < nck) {
            uint32_t s = sb + ((i + 1) & 1) * SS;
            const int k0 = (i + 1) * 32;
            cp_tile<128>(pAh, lda, k0, s);
            cp_tile<128>(pAl, lda, k0, s + 10240);
            cp_tile<BN >(pBh, ldb, k0, s + 20480);
            cp_tile<BN >(pBl, ldb, k0, s + 20480 + BN * 80);
            CP_COMMIT();
            CP_WAIT1();
        } else {
            CP_WAIT0();
        }
        __syncthreads();

        const uint32_t st = sb + (i & 1) * SS;
        #pragma unroll
        for (int ks = 0; ks < 2; ks++) {
            uint32_t af[2][2][4];
            #pragma unroll
            for (int mt = 0; mt < 2; mt++)
                #pragma unroll
                for (int hl = 0; hl < 2; hl++)
                    ldsm4(af[mt][hl], st + hl * 10240 + (aRow + mt * 16) * 80 + aColB + ks * 32);
            #pragma unroll
            for (int p = 0; p < NP; p++) {
                uint32_t bh4[4], bl4[4];
                uint32_t boff = st + 20480 + (bRow + p * 16) * 80 + aColB + ks * 32;
                ldsm4(bh4, boff);
                ldsm4(bl4, boff + BN * 80);
                #pragma unroll
                for (int mt = 0; mt < 2; mt++)
                    #pragma unroll
                    for (int sub = 0; sub < 2; sub++) {
                        uint32_t bh2[2] = { bh4[sub], bh4[sub + 2] };
                        uint32_t bl2[2] = { bl4[sub], bl4[sub + 2] };
                        float* c = acc[mt][p * 2 + sub];
                        mma16816(c, af[mt][0], bh2);   // hi*hi
                        mma16816(c, af[mt][0], bl2);   // hi*lo
                        mma16816(c, af[mt][1], bh2);   // lo*hi
                    }
            }
        }
        __syncthreads();
    }

    // ---------------- epilogue ----------------
    const long long cOff = (long long)zo * cSO + (long long)zh * cSH;
    const int rbase = m0 + wm * 32 + (lane >> 2);
    const int cbase = n0 + wn * (BN / 2) + 2 * (lane & 3);
    #pragma unroll
    for (int mt = 0; mt < 2; mt++)
        #pragma unroll
        for (int nt = 0; nt < NTL; nt++)
            #pragma unroll
            for (int hf = 0; hf < 2; hf++) {
                const int row = rbase + mt * 16 + hf * 8;
                const int col = cbase + nt * 8;
                float v0 = acc[mt][nt][hf * 2 + 0] * alpha;
                float v1 = acc[mt][nt][hf * 2 + 1] * alpha;
                if (EPI >= 1) {
                    float2 bb = *(const float2*)(bias + col);
                    v0 += bb.x; v1 += bb.y;
                }
                if (EPI == 2) { v0 = fmaxf(v0, 0.f); v1 = fmaxf(v1, 0.f); }
                if (EPI == 3) {
                    float2 rr = *(const float2*)(res + (long long)row * ldres + col);
                    v0 += rr.x; v1 += rr.y;
                }
                const long long o = cOff + (long long)row * ldc + col;
                if (WF32) { float2 w{v0, v1}; *(float2*)(C + o) = w; }
                if (WBF16) {
                    bf16 h0, h1, l0, l1;
                    bsplit(v0, h0, l0); bsplit(v1, h1, l1);
                    bf162 hh{h0, h1}, ll{l0, l1};
                    *(bf162*)(Ch + o) = hh;
                    *(bf162*)(Cl + o) = ll;
                }
            }
}

// ---------------- fp32 -> split bf16 ----------------
__global__ void __launch_bounds__(256)
split_kernel(const float* __restrict__ in, bf16* __restrict__ oh, bf16* __restrict__ ol, int n)
{
    int i = (blockIdx.x * 256 + threadIdx.x) * 4;
    if (i >= n) return;
    float4 v = *(const float4*)(in + i);
    bf16 h0, h1, h2, h3, l0, l1, l2, l3;
    bsplit(v.x, h0, l0); bsplit(v.y, h1, l1); bsplit(v.z, h2, l2); bsplit(v.w, h3, l3);
    bf162 a0{h0, h1}, a1{h2, h3}, b0{l0, l1}, b1{l2, l3};
    *(bf162*)(oh + i) = a0; *(bf162*)(oh + i + 2) = a1;
    *(bf162*)(ol + i) = b0; *(bf162*)(ol + i + 2) = b1;
}

// ---------------- W[Kd,Nd] fp32 -> WT[Nd,Kd] split bf16 ----------------
__global__ void __launch_bounds__(256)
tsplit_kernel(const float* __restrict__ W, bf16* __restrict__ th_, bf16* __restrict__ tl_,
              int Kd, int Nd)
{
    __shared__ float tile[32][33];
    const int n0 = blockIdx.x * 32, k0 = blockIdx.y * 32;
    const int tx = threadIdx.x & 31, ty = threadIdx.x >> 5;
    #pragma unroll
    for (int i = 0; i < 4; i++)
        tile[ty + 8 * i][tx] = W[(long long)(k0 + ty + 8 * i) * Nd + n0 + tx];
    __syncthreads();
    #pragma unroll
    for (int i = 0; i < 4; i++) {
        float v = tile[tx][ty + 8 * i];
        bf16 h, l; bsplit(v, h, l);
        long long o = (long long)(n0 + ty + 8 * i) * Kd + k0 + tx;
        th_[o] = h; tl_[o] = l;
    }
}

// ---------------- V^T: qkv split -> Vt [bh][64][2048] ----------------
__global__ void __launch_bounds__(256)
vt_kernel(const bf16* __restrict__ qh, const bf16* __restrict__ ql,
          bf16* __restrict__ vh, bf16* __restrict__ vl)
{
    __shared__ bf16 th[32][34], tl[32][34];
    const int bh = blockIdx.z;
    const int s0 = blockIdx.x * 32, d0 = blockIdx.y * 32;
    const int tx = threadIdx.x & 31, ty = threadIdx.x >> 5;
    const long long src = (long long)(bh >> 4) * SEQ * QKVW + (long long)(bh & 15) * 192 + 128;
    #pragma unroll
    for (int i = 0; i < 4; i++) {
        long long g = src + (long long)(s0 + ty + 8 * i) * QKVW + d0 + tx;
        th[ty + 8 * i][tx] = qh[g];
        tl[ty + 8 * i][tx] = ql[g];
    }
    __syncthreads();
    const long long dst = (long long)bh * HDIM * SEQ;
    #pragma unroll
    for (int i = 0; i < 4; i++) {
        long long o = dst + (long long)(d0 + ty + 8 * i) * SEQ + s0 + tx;
        vh[o] = th[tx][ty + 8 * i];
        vl[o] = tl[tx][ty + 8 * i];
    }
}

// ---------------- softmax (2048 cols): fp32 in -> split bf16 out ----------------
__global__ void __launch_bounds__(256)
softmax_split_kernel(const float* __restrict__ sc, bf16* __restrict__ ph_, bf16* __restrict__ pl_)
{
    __shared__ float sred[8];
    __shared__ float bc;
    const long long row = blockIdx.x;
    const float* p = sc + row * (long long)SEQ;
    const int t = threadIdx.x;

    float v[8];
    float mx = -1e30f;
    #pragma unroll
    for (int i = 0; i < 8; i++) { v[i] = p[t + i * 256]; mx = fmaxf(mx, v[i]); }
    mx = warpMax(mx);
    if ((t & 31) == 0) sred[t >> 5] = mx;
    __syncthreads();
    if (t < 32) { float x = (t < 8) ? sred[t] : -1e30f; x = warpMax(x); if (t == 0) bc = x; }
    __syncthreads();
    mx = bc;

    float sum = 0.0f;
    #pragma unroll
    for (int i = 0; i < 8; i++) { v[i] = expf(v[i] - mx); sum += v[i]; }
    sum = warpSum(sum);
    if ((t & 31) == 0) sred[t >> 5] = sum;
    __syncthreads();
    if (t < 32) { float x = (t < 8) ? sred[t] : 0.0f; x = warpSum(x); if (t == 0) bc = x; }
    __syncthreads();
    const float inv = 1.0f / bc;

    #pragma unroll
    for (int i = 0; i < 8; i++) {
        bf16 h, l; bsplit(v[i] * inv, h, l);
        ph_[row * (long long)SEQ + t + i * 256] = h;
        pl_[row * (long long)SEQ + t + i * 256] = l;
    }
}

// ---------------- LayerNorm (D=1024); optional split bf16 out ----------------
__global__ void __launch_bounds__(256)
ln_kernel(const float* __restrict__ in, const float* __restrict__ gamma,
          const float* __restrict__ beta, float* __restrict__ out,
          bf16* __restrict__ oh, bf16* __restrict__ ol)
{
    __shared__ float sred[8];
    __shared__ float bc;
    const long long row = blockIdx.x;
    const int t = threadIdx.x;

    float4 v = *(const float4*)(in + row * (long long)DMODEL + t * 4);
    float s = v.x + v.y + v.z + v.w;
    s = warpSum(s);
    if ((t & 31) == 0) sred[t >> 5] = s;
    __syncthreads();
    if (t < 32) { float x = (t < 8) ? sred[t] : 0.0f; x = warpSum(x); if (t == 0) bc = x; }
    __syncthreads();
    const float mean = bc * (1.0f / DMODEL);

    const float d0 = v.x - mean, d1 = v.y - mean, d2 = v.z - mean, d3 = v.w - mean;
    float sq = d0 * d0 + d1 * d1 + d2 * d2 + d3 * d3;
    sq = warpSum(sq);
    if ((t & 31) == 0) sred[t >> 5] = sq;
    __syncthreads();
    if (t < 32) { float x = (t < 8) ? sred[t] : 0.0f; x = warpSum(x); if (t == 0) bc = x; }
    __syncthreads();
    const float inv = rsqrtf(bc * (1.0f / DMODEL) + LNEPS);

    float4 gv = *(const float4*)(gamma + t * 4);
    float4 bv = *(const float4*)(beta + t * 4);
    float4 o;
    o.x = gv.x * d0 * inv + bv.x;
    o.y = gv.y * d1 * inv + bv.y;
    o.z = gv.z * d2 * inv + bv.z;
    o.w = gv.w * d3 * inv + bv.w;
    if (out) *(float4*)(out + row * (long long)DMODEL + t * 4) = o;
    if (oh) {
        bf16 h0, h1, h2, h3, l0, l1, l2, l3;
        bsplit(o.x, h0, l0); bsplit(o.y, h1, l1); bsplit(o.z, h2, l2); bsplit(o.w, h3, l3);
        bf162 a0{h0, h1}, a1{h2, h3}, b0{l0, l1}, b1{l2, l3};
        long long i = row * (long long)DMODEL + t * 4;
        *(bf162*)(oh + i) = a0; *(bf162*)(oh + i + 2) = a1;
        *(bf162*)(ol + i) = b0; *(bf162*)(ol + i + 2) = b1;
    }
}

// ---------------- launch ----------------
extern "C" void kernel_launch(void* const* d_in, const int* in_sizes, int n_in,
                              void* d_out, int out_size)
{
    const float* x      = (const float*)d_in[0];
    const float* W_qkv  = (const float*)d_in[1];
    const float* b_qkv  = (const float*)d_in[2];
    const float* W_o    = (const float*)d_in[3];
    const float* b_o    = (const float*)d_in[4];
    const float* gamma1 = (const float*)d_in[5];
    const float* beta1  = (const float*)d_in[6];
    const float* W1     = (const float*)d_in[7];
    const float* b1     = (const float*)d_in[8];
    const float* W2     = (const float*)d_in[9];
    const float* b2     = (const float*)d_in[10];
    const float* gamma2 = (const float*)d_in[11];
    const float* beta2  = (const float*)d_in[12];
    float* out = (float*)d_out;

    float *scores, *attn, *hbuf, *f2;
    bf16 *xh, *xl, *WqTh, *WqTl, *WoTh, *WoTl, *W1Th, *W1Tl, *W2Th, *W2Tl;
    bf16 *qh, *ql, *vth, *vtl, *Ph, *Pl, *valh, *vall, *hh, *hl, *f1h, *f1l;
    cudaGetSymbolAddress((void**)&scores, g_scores);
    cudaGetSymbolAddress((void**)&attn, g_attn);
    cudaGetSymbolAddress((void**)&hbuf, g_hf);
    cudaGetSymbolAddress((void**)&f2,   g_f2);
    cudaGetSymbolAddress((void**)&xh, g_xh);      cudaGetSymbolAddress((void**)&xl, g_xl);
    cudaGetSymbolAddress((void**)&WqTh, g_WqT_h); cudaGetSymbolAddress((void**)&WqTl, g_WqT_l);
    cudaGetSymbolAddress((void**)&WoTh, g_WoT_h); cudaGetSymbolAddress((void**)&WoTl, g_WoT_l);
    cudaGetSymbolAddress((void**)&W1Th, g_W1T_h); cudaGetSymbolAddress((void**)&W1Tl, g_W1T_l);
    cudaGetSymbolAddress((void**)&W2Th, g_W2T_h); cudaGetSymbolAddress((void**)&W2Tl, g_W2T_l);
    cudaGetSymbolAddress((void**)&qh, g_qkv_h);   cudaGetSymbolAddress((void**)&ql, g_qkv_l);
    cudaGetSymbolAddress((void**)&vth, g_Vt_h);   cudaGetSymbolAddress((void**)&vtl, g_Vt_l);
    cudaGetSymbolAddress((void**)&Ph, g_P_h);     cudaGetSymbolAddress((void**)&Pl, g_P_l);
    cudaGetSymbolAddress((void**)&valh, g_vals_h); cudaGetSymbolAddress((void**)&vall, g_vals_l);
    cudaGetSymbolAddress((void**)&hh, g_h_h);     cudaGetSymbolAddress((void**)&hl, g_h_l);
    cudaGetSymbolAddress((void**)&f1h, g_f1_h);   cudaGetSymbolAddress((void**)&f1l, g_f1_l);

    const int SM128 = 2 * (20480 + 2 * 128 * 80);   // 81920
    const int SM64  = 2 * (20480 + 2 *  64 * 80);   // 61440
    cudaFuncSetAttribute(mm_gemm<128,1,false,true>, cudaFuncAttributeMaxDynamicSharedMemorySize, SM128);
    cudaFuncSetAttribute(mm_gemm<128,0,true,false>, cudaFuncAttributeMaxDynamicSharedMemorySize, SM128);
    cudaFuncSetAttribute(mm_gemm<64,0,false,true>,  cudaFuncAttributeMaxDynamicSharedMemorySize, SM64);
    cudaFuncSetAttribute(mm_gemm<128,2,false,true>, cudaFuncAttributeMaxDynamicSharedMemorySize, SM128);
    cudaFuncSetAttribute(mm_gemm<128,3,true,false>, cudaFuncAttributeMaxDynamicSharedMemorySize, SM128);

    const dim3 blk(256), gb(256);
    const long long qkvRow = (long long)SEQ * QKVW;
    const long long scB = (long long)NHEADS * SEQ * SEQ, scH = (long long)SEQ * SEQ;

    // 0) prep
    tsplit_kernel<<<dim3(QKVW/32, DMODEL/32), blk>>>(W_qkv, WqTh, WqTl, DMODEL, QKVW);
    tsplit_kernel<<<dim3(DMODEL/32, DMODEL/32), blk>>>(W_o, WoTh, WoTl, DMODEL, DMODEL);
    tsplit_kernel<<<dim3(FFN/32, DMODEL/32), blk>>>(W1, W1Th, W1Tl, DMODEL, FFN);
    tsplit_kernel<<<dim3(DMODEL/32, FFN/32), blk>>>(W2, W2Th, W2Tl, FFN, DMODEL);
    split_kernel<<<NTOK * DMODEL / 1024, blk>>>(x, xh, xl, NTOK * DMODEL);

    // 1) qkv = x @ Wqkv + b -> split bf16
    mm_gemm<128,1,false,true><<<dim3(QKVW/128, NTOK/128, 1), gb, SM128>>>(
        xh, xl, WqTh, WqTl, nullptr, qh, ql, b_qkv, nullptr,
        DMODEL, DMODEL, DMODEL, QKVW, 0, 1.0f, 1, 0,0,0,0,0,0);

    // 2) Vt transpose
    vt_kernel<<<dim3(SEQ/32, HDIM/32, BATCH*NHEADS), blk>>>(qh, ql, vth, vtl);

    // 3) scores = 0.125 * Q @ K^T (fp32)
    mm_gemm<128,0,true,false><<<dim3(SEQ/128, SEQ/128, BATCH*NHEADS), gb, SM128>>>(
        qh, ql, qh + HDIM, ql + HDIM, scores, nullptr, nullptr, nullptr, nullptr,
        HDIM, QKVW, QKVW, SEQ, 0, 0.125f, NHEADS,
        qkvRow, 3*HDIM, qkvRow, 3*HDIM, scB, scH);

    // 4) softmax -> split bf16 P
    softmax_split_kernel<<<BATCH*NHEADS*SEQ, blk>>>(scores, Ph, Pl);

    // 5) vals = P @ V -> split bf16, layout [b,s,h*64+d]
    mm_gemm<64,0,false,true><<<dim3(1, SEQ/128, BATCH*NHEADS), gb, SM64>>>(
        Ph, Pl, vth, vtl, nullptr, valh, vall, nullptr, nullptr,
        SEQ, SEQ, SEQ, DMODEL, 0, 1.0f, NHEADS,
        scB, scH, (long long)NHEADS*HDIM*SEQ, (long long)HDIM*SEQ,
        (long long)SEQ*DMODEL, HDIM);

    // 6) attn = vals @ Wo + b + x
    mm_gemm<128,3,true,false><<<dim3(DMODEL/128, NTOK/128, 1), gb, SM128>>>(
        valh, vall, WoTh, WoTl, attn, nullptr, nullptr, b_o, x,
        DMODEL, DMODEL, DMODEL, DMODEL, DMODEL, 1.0f, 1, 0,0,0,0,0,0);

    // 7) h = LN1(attn): fp32 + split
    ln_kernel<<<NTOK, blk>>>(attn, gamma1, beta1, hbuf, hh, hl);

    // 8) f1 = relu(h @ W1 + b1) -> split bf16
    mm_gemm<128,2,false,true><<<dim3(FFN/128, NTOK/128, 1), gb, SM128>>>(
        hh, hl, W1Th, W1Tl, nullptr, f1h, f1l, b1, nullptr,
        DMODEL, DMODEL, DMODEL, FFN, 0, 1.0f, 1, 0,0,0,0,0,0);

    // 9) f2 = f1 @ W2 + b2 + h
    mm_gemm<128,3,true,false><<<dim3(DMODEL/128, NTOK/128, 1), gb, SM128>>>(
        f1h, f1l, W2Th, W2Tl, f2, nullptr, nullptr, b2, hbuf,
        FFN, FFN, FFN, DMODEL, DMODEL, 1.0f, 1, 0,0,0,0,0,0);

    // 10) out = LN2(f2)
    ln_kernel<<<NTOK, blk>>>(f2, gamma2, beta2, out, nullptr, nullptr);
}

// round 14
// speedup vs baseline: 2.7777x; 1.2724x over previous
#include <cuda_runtime.h>
#include <cuda_bf16.h>
#include <math.h>
#include <stdint.h>

#define BATCH 2
#define SEQ 2048
#define DMODEL 1024
#define NHEADS 16
#define HDIM 64
#define FFN 4096
#define NTOK (BATCH * SEQ)
#define QKVW (3 * DMODEL)
#define LNEPS 1e-5f

typedef __nv_bfloat16 bf16;
typedef __nv_bfloat162 bf162;

// ---------------- static device scratch ----------------
__device__ float g_attn[(size_t)NTOK * DMODEL];
__device__ float g_hf[(size_t)NTOK * DMODEL];
__device__ float g_f2[(size_t)NTOK * DMODEL];
__device__ bf16 g_xh[(size_t)NTOK * DMODEL], g_xl[(size_t)NTOK * DMODEL];
__device__ bf16 g_WqT_h[(size_t)QKVW * DMODEL], g_WqT_l[(size_t)QKVW * DMODEL];
__device__ bf16 g_WoT_h[(size_t)DMODEL * DMODEL], g_WoT_l[(size_t)DMODEL * DMODEL];
__device__ bf16 g_W1T_h[(size_t)FFN * DMODEL], g_W1T_l[(size_t)FFN * DMODEL];
__device__ bf16 g_W2T_h[(size_t)DMODEL * FFN], g_W2T_l[(size_t)DMODEL * FFN];
__device__ bf16 g_qkv_h[(size_t)NTOK * QKVW], g_qkv_l[(size_t)NTOK * QKVW];
__device__ bf16 g_vals_h[(size_t)NTOK * DMODEL], g_vals_l[(size_t)NTOK * DMODEL];
__device__ bf16 g_h_h[(size_t)NTOK * DMODEL], g_h_l[(size_t)NTOK * DMODEL];
__device__ bf16 g_f1_h[(size_t)NTOK * FFN], g_f1_l[(size_t)NTOK * FFN];

// ---------------- helpers ----------------
__device__ __forceinline__ float warpSum(float v) {
    #pragma unroll
    for (int o = 16; o > 0; o >>= 1) v += __shfl_xor_sync(0xffffffffu, v, o);
    return v;
}
__device__ __forceinline__ void bsplit(float v, bf16& h, bf16& l) {
    h = __float2bfloat16(v);
    l = __float2bfloat16(v - __bfloat162float(h));
}

// ---------------- portable tensor-core primitives ----------------
__device__ __forceinline__ void ldsm4(uint32_t* r, uint32_t a) {
    asm volatile("ldmatrix.sync.aligned.m8n8.x4.shared.b16 {%0,%1,%2,%3}, [%4];"
                 : "=r"(r[0]), "=r"(r[1]), "=r"(r[2]), "=r"(r[3]) : "r"(a));
}
__device__ __forceinline__ void ldsm4t(uint32_t* r, uint32_t a) {
    asm volatile("ldmatrix.sync.aligned.m8n8.x4.trans.shared.b16 {%0,%1,%2,%3}, [%4];"
                 : "=r"(r[0]), "=r"(r[1]), "=r"(r[2]), "=r"(r[3]) : "r"(a));
}
__device__ __forceinline__ void mma16816(float* c, const uint32_t* a, const uint32_t* b) {
    asm volatile("mma.sync.aligned.m16n8k16.row.col.f32.bf16.bf16.f32 "
                 "{%0,%1,%2,%3}, {%4,%5,%6,%7}, {%8,%9}, {%0,%1,%2,%3};"
                 : "+f"(c[0]), "+f"(c[1]), "+f"(c[2]), "+f"(c[3])
                 : "r"(a[0]), "r"(a[1]), "r"(a[2]), "r"(a[3]), "r"(b[0]), "r"(b[1]));
}
__device__ __forceinline__ void cpasync16(uint32_t dst, const void* src) {
    asm volatile("cp.async.cg.shared.global [%0], [%1], 16;" :: "r"(dst), "l"(src));
}
#define CP_COMMIT() asm volatile("cp.async.commit_group;" ::: "memory")
#define CP_WAIT0()  asm volatile("cp.async.wait_group 0;" ::: "memory")
#define CP_WAIT1()  asm volatile("cp.async.wait_group 1;" ::: "memory")

// copy R x 32 bf16 tile (row stride ld elems, col offset k0) -> smem rows of 80B
template<int R>
__device__ __forceinline__ void cp_tile(const bf16* __restrict__ g, long long ld, int k0, uint32_t s)
{
    #pragma unroll
    for (int it = 0; it < R / 64; it++) {
        int idx = threadIdx.x + it * 256;
        int r = idx >> 2, c = idx & 3;
        cpasync16(s + r * 80 + c * 16, g + (long long)r * ld + k0 + c * 8);
    }
}

// =====================================================================
// mma.sync split-bf16 GEMM (unchanged from R13, verified)
// =====================================================================
template<int BN, int EPI, bool WF32, bool WBF16>
__global__ void __launch_bounds__(256)
mm_gemm(const bf16* __restrict__ Ah, const bf16* __restrict__ Al,
        const bf16* __restrict__ Bh, const bf16* __restrict__ Bl,
        float* __restrict__ C, bf16* __restrict__ Ch, bf16* __restrict__ Cl,
        const float* __restrict__ bias, const float* __restrict__ res,
        int K, long long lda, long long ldb, long long ldc, long long ldres,
        float alpha)
{
    constexpr int SS  = 20480 + 2 * BN * 80;
    constexpr int NTL = BN / 16;
    constexpr int NP  = BN / 32;

    extern __shared__ char sm[];
    const uint32_t sb = (uint32_t)__cvta_generic_to_shared(sm);

    const int tid = threadIdx.x, lane = tid & 31, wid = tid >> 5;
    const int wm = wid >> 1, wn = wid & 1;
    const int m0 = blockIdx.y * 128, n0 = blockIdx.x * BN;

    const bf16* pAh = Ah + (long long)m0 * lda;
    const bf16* pAl = Al + (long long)m0 * lda;
    const bf16* pBh = Bh + (long long)n0 * ldb;
    const bf16* pBl = Bl + (long long)n0 * ldb;

    float acc[2][NTL][4];
    #pragma unroll
    for (int i = 0; i < 2; i++)
        #pragma unroll
        for (int j = 0; j < NTL; j++)
            #pragma unroll
            for (int c = 0; c < 4; c++) acc[i][j][c] = 0.0f;

    const int nck = K >> 5;
    {
        uint32_t s = sb;
        cp_tile<128>(pAh, lda, 0, s);
        cp_tile<128>(pAl, lda, 0, s + 10240);
        cp_tile<BN >(pBh, ldb, 0, s + 20480);
        cp_tile<BN >(pBl, ldb, 0, s + 20480 + BN * 80);
    }
    CP_COMMIT();

    const uint32_t aRow  = (uint32_t)(wm * 32 + (lane & 15));
    const uint32_t aColB = (uint32_t)((lane >> 4) * 16);
    const uint32_t bRow  = (uint32_t)(wn * (BN / 2) + (lane & 15));

    for (int i = 0; i < nck; i++) {
        if (i + 1 < nck) {
            uint32_t s = sb + ((i + 1) & 1) * SS;
            const int k0 = (i + 1) * 32;
            cp_tile<128>(pAh, lda, k0, s);
            cp_tile<128>(pAl, lda, k0, s + 10240);
            cp_tile<BN >(pBh, ldb, k0, s + 20480);
            cp_tile<BN >(pBl, ldb, k0, s + 20480 + BN * 80);
            CP_COMMIT();
            CP_WAIT1();
        } else {
            CP_WAIT0();
        }
        __syncthreads();

        const uint32_t st = sb + (i & 1) * SS;
        #pragma unroll
        for (int ks = 0; ks < 2; ks++) {
            uint32_t af[2][2][4];
            #pragma unroll
            for (int mt = 0; mt < 2; mt++)
                #pragma unroll
                for (int hl = 0; hl < 2; hl++)
                    ldsm4(af[mt][hl], st + hl * 10240 + (aRow + mt * 16) * 80 + aColB + ks * 32);
            #pragma unroll
            for (int p = 0; p < NP; p++) {
                uint32_t bh4[4], bl4[4];
                uint32_t boff = st + 20480 + (bRow + p * 16) * 80 + aColB + ks * 32;
                ldsm4(bh4, boff);
                ldsm4(bl4, boff + BN * 80);
                #pragma unroll
                for (int mt = 0; mt < 2; mt++)
                    #pragma unroll
                    for (int sub = 0; sub < 2; sub++) {
                        uint32_t bh2[2] = { bh4[sub], bh4[sub + 2] };
                        uint32_t bl2[2] = { bl4[sub], bl4[sub + 2] };
                        float* c = acc[mt][p * 2 + sub];
                        mma16816(c, af[mt][0], bh2);
                        mma16816(c, af[mt][0], bl2);
                        mma16816(c, af[mt][1], bh2);
                    }
            }
        }
        __syncthreads();
    }

    const int rbase = m0 + wm * 32 + (lane >> 2);
    const int cbase = n0 + wn * (BN / 2) + 2 * (lane & 3);
    #pragma unroll
    for (int mt = 0; mt < 2; mt++)
        #pragma unroll
        for (int nt = 0; nt < NTL; nt++)
            #pragma unroll
            for (int hf = 0; hf < 2; hf++) {
                const int row = rbase + mt * 16 + hf * 8;
                const int col = cbase + nt * 8;
                float v0 = acc[mt][nt][hf * 2 + 0] * alpha;
                float v1 = acc[mt][nt][hf * 2 + 1] * alpha;
                if (EPI >= 1) {
                    float2 bb = *(const float2*)(bias + col);
                    v0 += bb.x; v1 += bb.y;
                }
                if (EPI == 2) { v0 = fmaxf(v0, 0.f); v1 = fmaxf(v1, 0.f); }
                if (EPI == 3) {
                    float2 rr = *(const float2*)(res + (long long)row * ldres + col);
                    v0 += rr.x; v1 += rr.y;
                }
                const long long o = (long long)row * ldc + col;
                if (WF32) { float2 w{v0, v1}; *(float2*)(C + o) = w; }
                if (WBF16) {
                    bf16 h0, h1, l0, l1;
                    bsplit(v0, h0, l0); bsplit(v1, h1, l1);
                    bf162 hh{h0, h1}, ll{l0, l1};
                    *(bf162*)(Ch + o) = hh;
                    *(bf162*)(Cl + o) = ll;
                }
            }
}

// =====================================================================
// Fused flash attention (plain bf16 Q/K/P/V, fp32 softmax state + O acc)
// grid (SEQ/128, BATCH*NHEADS), 256 thr = 8 warps, warp owns 16 q-rows.
// Q/K tiles [128][64] pad->144B rows; V tile raw [128 kv][64 d] 144B rows.
// Writes vals (split hi/lo bf16) in [tok][DMODEL] layout at head offset.
// =====================================================================
__global__ void __launch_bounds__(256)
flash_kernel(const bf16* __restrict__ qkv, bf16* __restrict__ Oh, bf16* __restrict__ Ol)
{
    extern __shared__ char sm[];
    const uint32_t sb = (uint32_t)__cvta_generic_to_shared(sm);
    // layout: Q [0, 18432); stage st: K at 18432 + st*36864, V at +18432
    const int tid = threadIdx.x, lane = tid & 31, w = tid >> 5;
    const int qb = blockIdx.x, bh = blockIdx.y;
    const int b = bh >> 4, h = bh & 15;

    const bf16* qbase = qkv + ((long long)b * SEQ + qb * 128) * QKVW + h * 192;

    // Q load (grouped with stage 0)
    #pragma unroll
    for (int it = 0; it < 4; it++) {
        int idx = tid + it * 256; int r = idx >> 3, c = idx & 7;
        cpasync16(sb + r * 144 + c * 16, qbase + (long long)r * QKVW + c * 8);
    }
    auto loadKV = [&](int j, int st) {
        const bf16* kb = qkv + ((long long)b * SEQ + j * 128) * QKVW + h * 192 + 64;
        uint32_t s = sb + 18432 + st * 36864;
        #pragma unroll
        for (int it = 0; it < 4; it++) {
            int idx = tid + it * 256; int r = idx >> 3, c = idx & 7;
            cpasync16(s + r * 144 + c * 16, kb + (long long)r * QKVW + c * 8);
        }
        #pragma unroll
        for (int it = 0; it < 4; it++) {
            int idx = tid + it * 256; int r = idx >> 3, c = idx & 7;
            cpasync16(s + 18432 + r * 144 + c * 16, kb + 64 + (long long)r * QKVW + c * 8);
        }
    };
    loadKV(0, 0); CP_COMMIT();
    loadKV(1, 1); CP_COMMIT();

    uint32_t qf[4][4];
    float oacc[8][4];
    #pragma unroll
    for (int i = 0; i < 8; i++)
        #pragma unroll
        for (int c = 0; c < 4; c++) oacc[i][c] = 0.0f;
    float m0r = -1e30f, m1r = -1e30f, l0r = 0.0f, l1r = 0.0f;

    for (int j = 0; j < SEQ / 128; j++) {
        if (j < SEQ / 128 - 1) CP_WAIT1(); else CP_WAIT0();
        __syncthreads();
        if (j == 0) {
            #pragma unroll
            for (int ks = 0; ks < 4; ks++)
                ldsm4(qf[ks], sb + (w * 16 + (lane & 15)) * 144 + (lane >> 4) * 16 + ks * 32);
        }
        const uint32_t kst = sb + 18432 + (j & 1) * 36864;

        // S = Q @ K^T  (16 x 128 per warp)
        float sacc[16][4];
        #pragma unroll
        for (int nt = 0; nt < 16; nt++)
            #pragma unroll
            for (int c = 0; c < 4; c++) sacc[nt][c] = 0.0f;
        #pragma unroll
        for (int np = 0; np < 8; np++)
            #pragma unroll
            for (int ks = 0; ks < 4; ks++) {
                uint32_t b4[4];
                ldsm4(b4, kst + (np * 16 + (lane & 15)) * 144 + (lane >> 4) * 16 + ks * 32);
                uint32_t b2a[2] = { b4[0], b4[2] }, b2b[2] = { b4[1], b4[3] };
                mma16816(sacc[np * 2],     qf[ks], b2a);
                mma16816(sacc[np * 2 + 1], qf[ks], b2b);
            }

        // online softmax
        float mx0 = -1e30f, mx1 = -1e30f;
        #pragma unroll
        for (int nt = 0; nt < 16; nt++) {
            sacc[nt][0] *= 0.125f; sacc[nt][1] *= 0.125f;
            sacc[nt][2] *= 0.125f; sacc[nt][3] *= 0.125f;
            mx0 = fmaxf(mx0, fmaxf(sacc[nt][0], sacc[nt][1]));
            mx1 = fmaxf(mx1, fmaxf(sacc[nt][2], sacc[nt][3]));
        }
        mx0 = fmaxf(mx0, __shfl_xor_sync(0xffffffffu, mx0, 1));
        mx0 = fmaxf(mx0, __shfl_xor_sync(0xffffffffu, mx0, 2));
        mx1 = fmaxf(mx1, __shfl_xor_sync(0xffffffffu, mx1, 1));
        mx1 = fmaxf(mx1, __shfl_xor_sync(0xffffffffu, mx1, 2));
        const float mn0 = fmaxf(m0r, mx0), mn1 = fmaxf(m1r, mx1);
        const float sc0 = __expf(m0r - mn0), sc1 = __expf(m1r - mn1);
        m0r = mn0; m1r = mn1;

        uint32_t pf[8][4];
        float sum0 = 0.0f, sum1 = 0.0f;
        #pragma unroll
        for (int kt = 0; kt < 8; kt++) {
            float p00 = __expf(sacc[2*kt][0] - mn0),   p01 = __expf(sacc[2*kt][1] - mn0);
            float p10 = __expf(sacc[2*kt][2] - mn1),   p11 = __expf(sacc[2*kt][3] - mn1);
            float p20 = __expf(sacc[2*kt+1][0] - mn0), p21 = __expf(sacc[2*kt+1][1] - mn0);
            float p30 = __expf(sacc[2*kt+1][2] - mn1), p31 = __expf(sacc[2*kt+1][3] - mn1);
            sum0 += p00 + p01 + p20 + p21;
            sum1 += p10 + p11 + p30 + p31;
            bf162 t0 = __floats2bfloat162_rn(p00, p01);
            bf162 t1 = __floats2bfloat162_rn(p10, p11);
            bf162 t2 = __floats2bfloat162_rn(p20, p21);
            bf162 t3 = __floats2bfloat162_rn(p30, p31);
            pf[kt][0] = *(uint32_t*)&t0; pf[kt][1] = *(uint32_t*)&t1;
            pf[kt][2] = *(uint32_t*)&t2; pf[kt][3] = *(uint32_t*)&t3;
        }
        sum0 += __shfl_xor_sync(0xffffffffu, sum0, 1);
        sum0 += __shfl_xor_sync(0xffffffffu, sum0, 2);
        sum1 += __shfl_xor_sync(0xffffffffu, sum1, 1);
        sum1 += __shfl_xor_sync(0xffffffffu, sum1, 2);
        l0r = l0r * sc0 + sum0;
        l1r = l1r * sc1 + sum1;
        #pragma unroll
        for (int od = 0; od < 8; od++) {
            oacc[od][0] *= sc0; oacc[od][1] *= sc0;
            oacc[od][2] *= sc1; oacc[od][3] *= sc1;
        }

        // O += P @ V  (V raw [kv][64]; B-frags via ldmatrix.trans)
        const uint32_t vst = kst + 18432;
        const uint32_t vrow = ((lane >> 3) & 1) * 8 + (lane & 7);
        const uint32_t vcolB = (lane >> 4) * 16;   // bytes: (lane>>4)*8 cols * 2B
        #pragma unroll
        for (int np = 0; np < 4; np++)
            #pragma unroll
            for (int kt = 0; kt < 8; kt++) {
                uint32_t b4[4];
                ldsm4t(b4, vst + (kt * 16 + vrow) * 144 + np * 32 + vcolB);
                uint32_t bA[2] = { b4[0], b4[1] }, bB[2] = { b4[2], b4[3] };
                mma16816(oacc[np * 2],     pf[kt], bA);
                mma16816(oacc[np * 2 + 1], pf[kt], bB);
            }

        __syncthreads();
        if (j + 2 < SEQ / 128) { loadKV(j + 2, j & 1); CP_COMMIT(); }
    }

    // epilogue: normalize, split, store
    const float inv0 = 1.0f / l0r, inv1 = 1.0f / l1r;
    const long long tok0 = (long long)b * SEQ + qb * 128 + w * 16 + (lane >> 2);
    #pragma unroll
    for (int od = 0; od < 8; od++) {
        const int col = h * 64 + od * 8 + 2 * (lane & 3);
        {
            float v0 = oacc[od][0] * inv0, v1 = oacc[od][1] * inv0;
            bf16 h0, h1, l0, l1; bsplit(v0, h0, l0); bsplit(v1, h1, l1);
            bf162 hh{h0, h1}, ll{l0, l1};
            long long o = tok0 * DMODEL + col;
            *(bf162*)(Oh + o) = hh; *(bf162*)(Ol + o) = ll;
        }
        {
            float v0 = oacc[od][2] * inv1, v1 = oacc[od][3] * inv1;
            bf16 h0, h1, l0, l1; bsplit(v0, h0, l0); bsplit(v1, h1, l1);
            bf162 hh{h0, h1}, ll{l0, l1};
            long long o = (tok0 + 8) * DMODEL + col;
            *(bf162*)(Oh + o) = hh; *(bf162*)(Ol + o) = ll;
        }
    }
}

// ---------------- fp32 -> split bf16 ----------------
__global__ void __launch_bounds__(256)
split_kernel(const float* __restrict__ in, bf16* __restrict__ oh, bf16* __restrict__ ol, int n)
{
    int i = (blockIdx.x * 256 + threadIdx.x) * 4;
    if (i >= n) return;
    float4 v = *(const float4*)(in + i);
    bf16 h0, h1, h2, h3, l0, l1, l2, l3;
    bsplit(v.x, h0, l0); bsplit(v.y, h1, l1); bsplit(v.z, h2, l2); bsplit(v.w, h3, l3);
    bf162 a0{h0, h1}, a1{h2, h3}, b0{l0, l1}, b1{l2, l3};
    *(bf162*)(oh + i) = a0; *(bf162*)(oh + i + 2) = a1;
    *(bf162*)(ol + i) = b0; *(bf162*)(ol + i + 2) = b1;
}

// ---------------- W[Kd,Nd] fp32 -> WT[Nd,Kd] split bf16 ----------------
__global__ void __launch_bounds__(256)
tsplit_kernel(const float* __restrict__ W, bf16* __restrict__ th_, bf16* __restrict__ tl_,
              int Kd, int Nd)
{
    __shared__ float tile[32][33];
    const int n0 = blockIdx.x * 32, k0 = blockIdx.y * 32;
    const int tx = threadIdx.x & 31, ty = threadIdx.x >> 5;
    #pragma unroll
    for (int i = 0; i < 4; i++)
        tile[ty + 8 * i][tx] = W[(long long)(k0 + ty + 8 * i) * Nd + n0 + tx];
    __syncthreads();
    #pragma unroll
    for (int i = 0; i < 4; i++) {
        float v = tile[tx][ty + 8 * i];
        bf16 h, l; bsplit(v, h, l);
        long long o = (long long)(n0 + ty + 8 * i) * Kd + k0 + tx;
        th_[o] = h; tl_[o] = l;
    }
}

// ---------------- LayerNorm (D=1024); optional split bf16 out ----------------
__global__ void __launch_bounds__(256)
ln_kernel(const float* __restrict__ in, const float* __restrict__ gamma,
          const float* __restrict__ beta, float* __restrict__ out,
          bf16* __restrict__ oh, bf16* __restrict__ ol)
{
    __shared__ float sred[8];
    __shared__ float bc;
    const long long row = blockIdx.x;
    const int t = threadIdx.x;

    float4 v = *(const float4*)(in + row * (long long)DMODEL + t * 4);
    float s = v.x + v.y + v.z + v.w;
    s = warpSum(s);
    if ((t & 31) == 0) sred[t >> 5] = s;
    __syncthreads();
    if (t < 32) { float x = (t < 8) ? sred[t] : 0.0f; x = warpSum(x); if (t == 0) bc = x; }
    __syncthreads();
    const float mean = bc * (1.0f / DMODEL);

    const float d0 = v.x - mean, d1 = v.y - mean, d2 = v.z - mean, d3 = v.w - mean;
    float sq = d0 * d0 + d1 * d1 + d2 * d2 + d3 * d3;
    sq = warpSum(sq);
    if ((t & 31) == 0) sred[t >> 5] = sq;
    __syncthreads();
    if (t < 32) { float x = (t < 8) ? sred[t] : 0.0f; x = warpSum(x); if (t == 0) bc = x; }
    __syncthreads();
    const float inv = rsqrtf(bc * (1.0f / DMODEL) + LNEPS);

    float4 gv = *(const float4*)(gamma + t * 4);
    float4 bv = *(const float4*)(beta + t * 4);
    float4 o;
    o.x = gv.x * d0 * inv + bv.x;
    o.y = gv.y * d1 * inv + bv.y;
    o.z = gv.z * d2 * inv + bv.z;
    o.w = gv.w * d3 * inv + bv.w;
    if (out) *(float4*)(out + row * (long long)DMODEL + t * 4) = o;
    if (oh) {
        bf16 h0, h1, h2, h3, l0, l1, l2, l3;
        bsplit(o.x, h0, l0); bsplit(o.y, h1, l1); bsplit(o.z, h2, l2); bsplit(o.w, h3, l3);
        bf162 a0{h0, h1}, a1{h2, h3}, b0{l0, l1}, b1{l2, l3};
        long long i = row * (long long)DMODEL + t * 4;
        *(bf162*)(oh + i) = a0; *(bf162*)(oh + i + 2) = a1;
        *(bf162*)(ol + i) = b0; *(bf162*)(ol + i + 2) = b1;
    }
}

// ---------------- launch ----------------
extern "C" void kernel_launch(void* const* d_in, const int* in_sizes, int n_in,
                              void* d_out, int out_size)
{
    const float* x      = (const float*)d_in[0];
    const float* W_qkv  = (const float*)d_in[1];
    const float* b_qkv  = (const float*)d_in[2];
    const float* W_o    = (const float*)d_in[3];
    const float* b_o    = (const float*)d_in[4];
    const float* gamma1 = (const float*)d_in[5];
    const float* beta1  = (const float*)d_in[6];
    const float* W1     = (const float*)d_in[7];
    const float* b1     = (const float*)d_in[8];
    const float* W2     = (const float*)d_in[9];
    const float* b2     = (const float*)d_in[10];
    const float* gamma2 = (const float*)d_in[11];
    const float* beta2  = (const float*)d_in[12];
    float* out = (float*)d_out;

    float *attn, *hbuf, *f2;
    bf16 *xh, *xl, *WqTh, *WqTl, *WoTh, *WoTl, *W1Th, *W1Tl, *W2Th, *W2Tl;
    bf16 *qh, *ql, *valh, *vall, *hh, *hl, *f1h, *f1l;
    cudaGetSymbolAddress((void**)&attn, g_attn);
    cudaGetSymbolAddress((void**)&hbuf, g_hf);
    cudaGetSymbolAddress((void**)&f2,   g_f2);
    cudaGetSymbolAddress((void**)&xh, g_xh);      cudaGetSymbolAddress((void**)&xl, g_xl);
    cudaGetSymbolAddress((void**)&WqTh, g_WqT_h); cudaGetSymbolAddress((void**)&WqTl, g_WqT_l);
    cudaGetSymbolAddress((void**)&WoTh, g_WoT_h); cudaGetSymbolAddress((void**)&WoTl, g_WoT_l);
    cudaGetSymbolAddress((void**)&W1Th, g_W1T_h); cudaGetSymbolAddress((void**)&W1Tl, g_W1T_l);
    cudaGetSymbolAddress((void**)&W2Th, g_W2T_h); cudaGetSymbolAddress((void**)&W2Tl, g_W2T_l);
    cudaGetSymbolAddress((void**)&qh, g_qkv_h);   cudaGetSymbolAddress((void**)&ql, g_qkv_l);
    cudaGetSymbolAddress((void**)&valh, g_vals_h); cudaGetSymbolAddress((void**)&vall, g_vals_l);
    cudaGetSymbolAddress((void**)&hh, g_h_h);     cudaGetSymbolAddress((void**)&hl, g_h_l);
    cudaGetSymbolAddress((void**)&f1h, g_f1_h);   cudaGetSymbolAddress((void**)&f1l, g_f1_l);

    const int SM128 = 2 * (20480 + 2 * 128 * 80);   // 81920
    const int SMFL  = 18432 + 2 * 36864;            // 92160
    cudaFuncSetAttribute(mm_gemm<128,1,false,true>, cudaFuncAttributeMaxDynamicSharedMemorySize, SM128);
    cudaFuncSetAttribute(mm_gemm<128,2,false,true>, cudaFuncAttributeMaxDynamicSharedMemorySize, SM128);
    cudaFuncSetAttribute(mm_gemm<128,3,true,false>, cudaFuncAttributeMaxDynamicSharedMemorySize, SM128);
    cudaFuncSetAttribute(flash_kernel, cudaFuncAttributeMaxDynamicSharedMemorySize, SMFL);

    const dim3 blk(256), gb(256);

    // 0) prep
    tsplit_kernel<<<dim3(QKVW/32, DMODEL/32), blk>>>(W_qkv, WqTh, WqTl, DMODEL, QKVW);
    tsplit_kernel<<<dim3(DMODEL/32, DMODEL/32), blk>>>(W_o, WoTh, WoTl, DMODEL, DMODEL);
    tsplit_kernel<<<dim3(FFN/32, DMODEL/32), blk>>>(W1, W1Th, W1Tl, DMODEL, FFN);
    tsplit_kernel<<<dim3(DMODEL/32, FFN/32), blk>>>(W2, W2Th, W2Tl, FFN, DMODEL);
    split_kernel<<<NTOK * DMODEL / 1024, blk>>>(x, xh, xl, NTOK * DMODEL);

    // 1) qkv = x @ Wqkv + b -> split bf16
    mm_gemm<128,1,false,true><<<dim3(QKVW/128, NTOK/128, 1), gb, SM128>>>(
        xh, xl, WqTh, WqTl, nullptr, qh, ql, b_qkv, nullptr,
        DMODEL, DMODEL, DMODEL, QKVW, 0, 1.0f);

    // 2) fused flash attention -> vals (split bf16, [tok][DMODEL])
    flash_kernel<<<dim3(SEQ/128, BATCH*NHEADS), gb, SMFL>>>(qh, valh, vall);

    // 3) attn = vals @ Wo + b + x (residual)
    mm_gemm<128,3,true,false><<<dim3(DMODEL/128, NTOK/128, 1), gb, SM128>>>(
        valh, vall, WoTh, WoTl, attn, nullptr, nullptr, b_o, x,
        DMODEL, DMODEL, DMODEL, DMODEL, DMODEL, 1.0f);

    // 4) h = LN1(attn): fp32 + split
    ln_kernel<<<NTOK, blk>>>(attn, gamma1, beta1, hbuf, hh, hl);

    // 5) f1 = relu(h @ W1 + b1) -> split bf16
    mm_gemm<128,2,false,true><<<dim3(FFN/128, NTOK/128, 1), gb, SM128>>>(
        hh, hl, W1Th, W1Tl, nullptr, f1h, f1l, b1, nullptr,
        DMODEL, DMODEL, DMODEL, FFN, 0, 1.0f);

    // 6) f2 = f1 @ W2 + b2 + h
    mm_gemm<128,3,true,false><<<dim3(DMODEL/128, NTOK/128, 1), gb, SM128>>>(
        f1h, f1l, W2Th, W2Tl, f2, nullptr, nullptr, b2, hbuf,
        FFN, FFN, FFN, DMODEL, DMODEL, 1.0f);

    // 7) out = LN2(f2)
    ln_kernel<<<NTOK, blk>>>(f2, gamma2, beta2, out, nullptr, nullptr);
}

// round 15
// speedup vs baseline: 4.0847x; 1.4705x over previous
#include <cuda_runtime.h>
#include <cuda_fp16.h>
#include <math.h>
#include <stdint.h>

#define BATCH 2
#define SEQ 2048
#define DMODEL 1024
#define NHEADS 16
#define HDIM 64
#define FFN 4096
#define NTOK (BATCH * SEQ)
#define QKVW (3 * DMODEL)
#define LNEPS 1e-5f

typedef __half fp16;

// ---------------- static device scratch ----------------
__device__ float g_attn[(size_t)NTOK * DMODEL];
__device__ float g_hf[(size_t)NTOK * DMODEL];
__device__ float g_f2[(size_t)NTOK * DMODEL];
__device__ fp16 g_x16[(size_t)NTOK * DMODEL];
__device__ fp16 g_WqT_h[(size_t)QKVW * DMODEL], g_WqT_l[(size_t)QKVW * DMODEL];
__device__ fp16 g_WoT_h[(size_t)DMODEL * DMODEL], g_WoT_l[(size_t)DMODEL * DMODEL];
__device__ fp16 g_W1T_h[(size_t)FFN * DMODEL], g_W1T_l[(size_t)FFN * DMODEL];
__device__ fp16 g_W2T_h[(size_t)DMODEL * FFN], g_W2T_l[(size_t)DMODEL * FFN];
__device__ fp16 g_qkv16[(size_t)NTOK * QKVW];
__device__ fp16 g_vals16[(size_t)NTOK * DMODEL];
__device__ fp16 g_h16[(size_t)NTOK * DMODEL];
__device__ fp16 g_f116[(size_t)NTOK * FFN];

// ---------------- helpers ----------------
__device__ __forceinline__ float warpSum(float v) {
    #pragma unroll
    for (int o = 16; o > 0; o >>= 1) v += __shfl_xor_sync(0xffffffffu, v, o);
    return v;
}
__device__ __forceinline__ void hsplit(float v, fp16& h, fp16& l) {
    h = __float2half_rn(v);
    l = __float2half_rn(v - __half2float(h));
}

// ---------------- portable tensor-core primitives ----------------
__device__ __forceinline__ void ldsm4(uint32_t* r, uint32_t a) {
    asm volatile("ldmatrix.sync.aligned.m8n8.x4.shared.b16 {%0,%1,%2,%3}, [%4];"
                 : "=r"(r[0]), "=r"(r[1]), "=r"(r[2]), "=r"(r[3]) : "r"(a));
}
__device__ __forceinline__ void ldsm4t(uint32_t* r, uint32_t a) {
    asm volatile("ldmatrix.sync.aligned.m8n8.x4.trans.shared.b16 {%0,%1,%2,%3}, [%4];"
                 : "=r"(r[0]), "=r"(r[1]), "=r"(r[2]), "=r"(r[3]) : "r"(a));
}
__device__ __forceinline__ void mma16816(float* c, const uint32_t* a, const uint32_t* b) {
    asm volatile("mma.sync.aligned.m16n8k16.row.col.f32.f16.f16.f32 "
                 "{%0,%1,%2,%3}, {%4,%5,%6,%7}, {%8,%9}, {%0,%1,%2,%3};"
                 : "+f"(c[0]), "+f"(c[1]), "+f"(c[2]), "+f"(c[3])
                 : "r"(a[0]), "r"(a[1]), "r"(a[2]), "r"(a[3]), "r"(b[0]), "r"(b[1]));
}
__device__ __forceinline__ void cpasync16(uint32_t dst, const void* src) {
    asm volatile("cp.async.cg.shared.global [%0], [%1], 16;" :: "r"(dst), "l"(src));
}
#define CP_COMMIT() asm volatile("cp.async.commit_group;" ::: "memory")
#define CP_WAIT0()  asm volatile("cp.async.wait_group 0;" ::: "memory")
#define CP_WAIT1()  asm volatile("cp.async.wait_group 1;" ::: "memory")

// copy R x 32 fp16 tile (row stride ld elems, col offset k0) -> smem rows of 80B
template<int R>
__device__ __forceinline__ void cp_tile(const fp16* __restrict__ g, long long ld, int k0, uint32_t s)
{
    #pragma unroll
    for (int it = 0; it < R / 64; it++) {
        int idx = threadIdx.x + it * 256;
        int r = idx >> 2, c = idx & 3;
        cpasync16(s + r * 80 + c * 16, g + (long long)r * ld + k0 + c * 8);
    }
}

// =====================================================================
// mm_gemm: C = alpha * A[M,K](fp16) @ ((Bh+Bl)[N,K])^T   (2-product)
// BM=128, BN=128, BK=32; 256 thr = 8 warps (4M x 2N), warp tile 32x64.
// EPI: 1 +bias, 2 +bias+relu, 3 +bias+res
// =====================================================================
template<int BN, int EPI, bool WF32, bool WH>
__global__ void __launch_bounds__(256)
mm_gemm(const fp16* __restrict__ A,
        const fp16* __restrict__ Bh, const fp16* __restrict__ Bl,
        float* __restrict__ C, fp16* __restrict__ Ch,
        const float* __restrict__ bias, const float* __restrict__ res,
        int K, long long lda, long long ldb, long long ldc, long long ldres,
        float alpha)
{
    constexpr int SS  = 10240 + 2 * BN * 80;   // bytes per stage
    constexpr int NTL = BN / 16;
    constexpr int NP  = BN / 32;

    extern __shared__ char sm[];
    const uint32_t sb = (uint32_t)__cvta_generic_to_shared(sm);

    const int tid = threadIdx.x, lane = tid & 31, wid = tid >> 5;
    const int wm = wid >> 1, wn = wid & 1;
    const int m0 = blockIdx.y * 128, n0 = blockIdx.x * BN;

    const fp16* pA  = A  + (long long)m0 * lda;
    const fp16* pBh = Bh + (long long)n0 * ldb;
    const fp16* pBl = Bl + (long long)n0 * ldb;

    float acc[2][NTL][4];
    #pragma unroll
    for (int i = 0; i < 2; i++)
        #pragma unroll
        for (int j = 0; j < NTL; j++)
            #pragma unroll
            for (int c = 0; c < 4; c++) acc[i][j][c] = 0.0f;

    const int nck = K >> 5;
    {
        uint32_t s = sb;
        cp_tile<128>(pA,  lda, 0, s);
        cp_tile<BN >(pBh, ldb, 0, s + 10240);
        cp_tile<BN >(pBl, ldb, 0, s + 10240 + BN * 80);
    }
    CP_COMMIT();

    const uint32_t aRow  = (uint32_t)(wm * 32 + (lane & 15));
    const uint32_t aColB = (uint32_t)((lane >> 4) * 16);
    const uint32_t bRow  = (uint32_t)(wn * (BN / 2) + (lane & 15));

    for (int i = 0; i < nck; i++) {
        if (i + 1 < nck) {
            uint32_t s = sb + ((i + 1) & 1) * SS;
            const int k0 = (i + 1) * 32;
            cp_tile<128>(pA,  lda, k0, s);
            cp_tile<BN >(pBh, ldb, k0, s + 10240);
            cp_tile<BN >(pBl, ldb, k0, s + 10240 + BN * 80);
            CP_COMMIT();
            CP_WAIT1();
        } else {
            CP_WAIT0();
        }
        __syncthreads();

        const uint32_t st = sb + (i & 1) * SS;
        #pragma unroll
        for (int ks = 0; ks < 2; ks++) {
            uint32_t af[2][4];
            #pragma unroll
            for (int mt = 0; mt < 2; mt++)
                ldsm4(af[mt], st + (aRow + mt * 16) * 80 + aColB + ks * 32);
            #pragma unroll
            for (int p = 0; p < NP; p++) {
                uint32_t bh4[4], bl4[4];
                uint32_t boff = st + 10240 + (bRow + p * 16) * 80 + aColB + ks * 32;
                ldsm4(bh4, boff);
                ldsm4(bl4, boff + BN * 80);
                #pragma unroll
                for (int mt = 0; mt < 2; mt++)
                    #pragma unroll
                    for (int sub = 0; sub < 2; sub++) {
                        uint32_t bh2[2] = { bh4[sub], bh4[sub + 2] };
                        uint32_t bl2[2] = { bl4[sub], bl4[sub + 2] };
                        float* c = acc[mt][p * 2 + sub];
                        mma16816(c, af[mt], bh2);
                        mma16816(c, af[mt], bl2);
                    }
            }
        }
        __syncthreads();
    }

    const int rbase = m0 + wm * 32 + (lane >> 2);
    const int cbase = n0 + wn * (BN / 2) + 2 * (lane & 3);
    #pragma unroll
    for (int mt = 0; mt < 2; mt++)
        #pragma unroll
        for (int nt = 0; nt < NTL; nt++)
            #pragma unroll
            for (int hf = 0; hf < 2; hf++) {
                const int row = rbase + mt * 16 + hf * 8;
                const int col = cbase + nt * 8;
                float v0 = acc[mt][nt][hf * 2 + 0] * alpha;
                float v1 = acc[mt][nt][hf * 2 + 1] * alpha;
                if (EPI >= 1) {
                    float2 bb = *(const float2*)(bias + col);
                    v0 += bb.x; v1 += bb.y;
                }
                if (EPI == 2) { v0 = fmaxf(v0, 0.f); v1 = fmaxf(v1, 0.f); }
                if (EPI == 3) {
                    float2 rr = *(const float2*)(res + (long long)row * ldres + col);
                    v0 += rr.x; v1 += rr.y;
                }
                const long long o = (long long)row * ldc + col;
                if (WF32) { float2 w{v0, v1}; *(float2*)(C + o) = w; }
                if (WH)   { __half2 w = __floats2half2_rn(v0, v1); *(__half2*)(Ch + o) = w; }
            }
}

// =====================================================================
// Fused flash attention (fp16 Q/K/P/V, fp32 softmax state + O acc)
// grid (SEQ/128, BATCH*NHEADS), 256 thr = 8 warps, warp owns 16 q-rows.
// =====================================================================
__global__ void __launch_bounds__(256)
flash_kernel(const fp16* __restrict__ qkv, fp16* __restrict__ O)
{
    extern __shared__ char sm[];
    const uint32_t sb = (uint32_t)__cvta_generic_to_shared(sm);
    const int tid = threadIdx.x, lane = tid & 31, w = tid >> 5;
    const int qb = blockIdx.x, bh = blockIdx.y;
    const int b = bh >> 4, h = bh & 15;

    const fp16* qbase = qkv + ((long long)b * SEQ + qb * 128) * QKVW + h * 192;

    #pragma unroll
    for (int it = 0; it < 4; it++) {
        int idx = tid + it * 256; int r = idx >> 3, c = idx & 7;
        cpasync16(sb + r * 144 + c * 16, qbase + (long long)r * QKVW + c * 8);
    }
    auto loadKV = [&](int j, int st) {
        const fp16* kb = qkv + ((long long)b * SEQ + j * 128) * QKVW + h * 192 + 64;
        uint32_t s = sb + 18432 + st * 36864;
        #pragma unroll
        for (int it = 0; it < 4; it++) {
            int idx = tid + it * 256; int r = idx >> 3, c = idx & 7;
            cpasync16(s + r * 144 + c * 16, kb + (long long)r * QKVW + c * 8);
        }
        #pragma unroll
        for (int it = 0; it < 4; it++) {
            int idx = tid + it * 256; int r = idx >> 3, c = idx & 7;
            cpasync16(s + 18432 + r * 144 + c * 16, kb + 64 + (long long)r * QKVW + c * 8);
        }
    };
    loadKV(0, 0); CP_COMMIT();
    loadKV(1, 1); CP_COMMIT();

    uint32_t qf[4][4];
    float oacc[8][4];
    #pragma unroll
    for (int i = 0; i < 8; i++)
        #pragma unroll
        for (int c = 0; c < 4; c++) oacc[i][c] = 0.0f;
    float m0r = -1e30f, m1r = -1e30f, l0r = 0.0f, l1r = 0.0f;

    for (int j = 0; j < SEQ / 128; j++) {
        if (j < SEQ / 128 - 1) CP_WAIT1(); else CP_WAIT0();
        __syncthreads();
        if (j == 0) {
            #pragma unroll
            for (int ks = 0; ks < 4; ks++)
                ldsm4(qf[ks], sb + (w * 16 + (lane & 15)) * 144 + (lane >> 4) * 16 + ks * 32);
        }
        const uint32_t kst = sb + 18432 + (j & 1) * 36864;

        float sacc[16][4];
        #pragma unroll
        for (int nt = 0; nt < 16; nt++)
            #pragma unroll
            for (int c = 0; c < 4; c++) sacc[nt][c] = 0.0f;
        #pragma unroll
        for (int np = 0; np < 8; np++)
            #pragma unroll
            for (int ks = 0; ks < 4; ks++) {
                uint32_t b4[4];
                ldsm4(b4, kst + (np * 16 + (lane & 15)) * 144 + (lane >> 4) * 16 + ks * 32);
                uint32_t b2a[2] = { b4[0], b4[2] }, b2b[2] = { b4[1], b4[3] };
                mma16816(sacc[np * 2],     qf[ks], b2a);
                mma16816(sacc[np * 2 + 1], qf[ks], b2b);
            }

        float mx0 = -1e30f, mx1 = -1e30f;
        #pragma unroll
        for (int nt = 0; nt < 16; nt++) {
            sacc[nt][0] *= 0.125f; sacc[nt][1] *= 0.125f;
            sacc[nt][2] *= 0.125f; sacc[nt][3] *= 0.125f;
            mx0 = fmaxf(mx0, fmaxf(sacc[nt][0], sacc[nt][1]));
            mx1 = fmaxf(mx1, fmaxf(sacc[nt][2], sacc[nt][3]));
        }
        mx0 = fmaxf(mx0, __shfl_xor_sync(0xffffffffu, mx0, 1));
        mx0 = fmaxf(mx0, __shfl_xor_sync(0xffffffffu, mx0, 2));
        mx1 = fmaxf(mx1, __shfl_xor_sync(0xffffffffu, mx1, 1));
        mx1 = fmaxf(mx1, __shfl_xor_sync(0xffffffffu, mx1, 2));
        const float mn0 = fmaxf(m0r, mx0), mn1 = fmaxf(m1r, mx1);
        const float sc0 = __expf(m0r - mn0), sc1 = __expf(m1r - mn1);
        m0r = mn0; m1r = mn1;

        uint32_t pf[8][4];
        float sum0 = 0.0f, sum1 = 0.0f;
        #pragma unroll
        for (int kt = 0; kt < 8; kt++) {
            float p00 = __expf(sacc[2*kt][0] - mn0),   p01 = __expf(sacc[2*kt][1] - mn0);
            float p10 = __expf(sacc[2*kt][2] - mn1),   p11 = __expf(sacc[2*kt][3] - mn1);
            float p20 = __expf(sacc[2*kt+1][0] - mn0), p21 = __expf(sacc[2*kt+1][1] - mn0);
            float p30 = __expf(sacc[2*kt+1][2] - mn1), p31 = __expf(sacc[2*kt+1][3] - mn1);
            sum0 += p00 + p01 + p20 + p21;
            sum1 += p10 + p11 + p30 + p31;
            __half2 t0 = __floats2half2_rn(p00, p01);
            __half2 t1 = __floats2half2_rn(p10, p11);
            __half2 t2 = __floats2half2_rn(p20, p21);
            __half2 t3 = __floats2half2_rn(p30, p31);
            pf[kt][0] = *(uint32_t*)&t0; pf[kt][1] = *(uint32_t*)&t1;
            pf[kt][2] = *(uint32_t*)&t2; pf[kt][3] = *(uint32_t*)&t3;
        }
        sum0 += __shfl_xor_sync(0xffffffffu, sum0, 1);
        sum0 += __shfl_xor_sync(0xffffffffu, sum0, 2);
        sum1 += __shfl_xor_sync(0xffffffffu, sum1, 1);
        sum1 += __shfl_xor_sync(0xffffffffu, sum1, 2);
        l0r = l0r * sc0 + sum0;
        l1r = l1r * sc1 + sum1;
        #pragma unroll
        for (int od = 0; od < 8; od++) {
            oacc[od][0] *= sc0; oacc[od][1] *= sc0;
            oacc[od][2] *= sc1; oacc[od][3] *= sc1;
        }

        const uint32_t vst = kst + 18432;
        const uint32_t vrow = ((lane >> 3) & 1) * 8 + (lane & 7);
        const uint32_t vcolB = (lane >> 4) * 16;
        #pragma unroll
        for (int np = 0; np < 4; np++)
            #pragma unroll
            for (int kt = 0; kt < 8; kt++) {
                uint32_t b4[4];
                ldsm4t(b4, vst + (kt * 16 + vrow) * 144 + np * 32 + vcolB);
                uint32_t bA[2] = { b4[0], b4[1] }, bB[2] = { b4[2], b4[3] };
                mma16816(oacc[np * 2],     pf[kt], bA);
                mma16816(oacc[np * 2 + 1], pf[kt], bB);
            }

        __syncthreads();
        if (j + 2 < SEQ / 128) { loadKV(j + 2, j & 1); CP_COMMIT(); }
    }

    const float inv0 = 1.0f / l0r, inv1 = 1.0f / l1r;
    const long long tok0 = (long long)b * SEQ + qb * 128 + w * 16 + (lane >> 2);
    #pragma unroll
    for (int od = 0; od < 8; od++) {
        const int col = h * 64 + od * 8 + 2 * (lane & 3);
        {
            __half2 w2 = __floats2half2_rn(oacc[od][0] * inv0, oacc[od][1] * inv0);
            *(__half2*)(O + tok0 * DMODEL + col) = w2;
        }
        {
            __half2 w2 = __floats2half2_rn(oacc[od][2] * inv1, oacc[od][3] * inv1);
            *(__half2*)(O + (tok0 + 8) * DMODEL + col) = w2;
        }
    }
}

// ---------------- fp32 -> fp16 ----------------
__global__ void __launch_bounds__(256)
tohalf_kernel(const float* __restrict__ in, fp16* __restrict__ o, int n)
{
    int i = (blockIdx.x * 256 + threadIdx.x) * 4;
    if (i >= n) return;
    float4 v = *(const float4*)(in + i);
    __half2 a = __floats2half2_rn(v.x, v.y);
    __half2 b = __floats2half2_rn(v.z, v.w);
    *(__half2*)(o + i) = a; *(__half2*)(o + i + 2) = b;
}

// ---------------- W[Kd,Nd] fp32 -> WT[Nd,Kd] split fp16 ----------------
__global__ void __launch_bounds__(256)
tsplit_kernel(const float* __restrict__ W, fp16* __restrict__ th_, fp16* __restrict__ tl_,
              int Kd, int Nd)
{
    __shared__ float tile[32][33];
    const int n0 = blockIdx.x * 32, k0 = blockIdx.y * 32;
    const int tx = threadIdx.x & 31, ty = threadIdx.x >> 5;
    #pragma unroll
    for (int i = 0; i < 4; i++)
        tile[ty + 8 * i][tx] = W[(long long)(k0 + ty + 8 * i) * Nd + n0 + tx];
    __syncthreads();
    #pragma unroll
    for (int i = 0; i < 4; i++) {
        float v = tile[tx][ty + 8 * i];
        fp16 h, l; hsplit(v, h, l);
        long long o = (long long)(n0 + ty + 8 * i) * Kd + k0 + tx;
        th_[o] = h; tl_[o] = l;
    }
}

// ---------------- LayerNorm (D=1024); optional fp16 out ----------------
__global__ void __launch_bounds__(256)
ln_kernel(const float* __restrict__ in, const float* __restrict__ gamma,
          const float* __restrict__ beta, float* __restrict__ out,
          fp16* __restrict__ oh)
{
    __shared__ float sred[8];
    __shared__ float bc;
    const long long row = blockIdx.x;
    const int t = threadIdx.x;

    float4 v = *(const float4*)(in + row * (long long)DMODEL + t * 4);
    float s = v.x + v.y + v.z + v.w;
    s = warpSum(s);
    if ((t & 31) == 0) sred[t >> 5] = s;
    __syncthreads();
    if (t < 32) { float x = (t < 8) ? sred[t] : 0.0f; x = warpSum(x); if (t == 0) bc = x; }
    __syncthreads();
    const float mean = bc * (1.0f / DMODEL);

    const float d0 = v.x - mean, d1 = v.y - mean, d2 = v.z - mean, d3 = v.w - mean;
    float sq = d0 * d0 + d1 * d1 + d2 * d2 + d3 * d3;
    sq = warpSum(sq);
    if ((t & 31) == 0) sred[t >> 5] = sq;
    __syncthreads();
    if (t < 32) { float x = (t < 8) ? sred[t] : 0.0f; x = warpSum(x); if (t == 0) bc = x; }
    __syncthreads();
    const float inv = rsqrtf(bc * (1.0f / DMODEL) + LNEPS);

    float4 gv = *(const float4*)(gamma + t * 4);
    float4 bv = *(const float4*)(beta + t * 4);
    float4 o;
    o.x = gv.x * d0 * inv + bv.x;
    o.y = gv.y * d1 * inv + bv.y;
    o.z = gv.z * d2 * inv + bv.z;
    o.w = gv.w * d3 * inv + bv.w;
    if (out) *(float4*)(out + row * (long long)DMODEL + t * 4) = o;
    if (oh) {
        __half2 a = __floats2half2_rn(o.x, o.y);
        __half2 b = __floats2half2_rn(o.z, o.w);
        long long i = row * (long long)DMODEL + t * 4;
        *(__half2*)(oh + i) = a; *(__half2*)(oh + i + 2) = b;
    }
}

// ---------------- launch ----------------
extern "C" void kernel_launch(void* const* d_in, const int* in_sizes, int n_in,
                              void* d_out, int out_size)
{
    const float* x      = (const float*)d_in[0];
    const float* W_qkv  = (const float*)d_in[1];
    const float* b_qkv  = (const float*)d_in[2];
    const float* W_o    = (const float*)d_in[3];
    const float* b_o    = (const float*)d_in[4];
    const float* gamma1 = (const float*)d_in[5];
    const float* beta1  = (const float*)d_in[6];
    const float* W1     = (const float*)d_in[7];
    const float* b1     = (const float*)d_in[8];
    const float* W2     = (const float*)d_in[9];
    const float* b2     = (const float*)d_in[10];
    const float* gamma2 = (const float*)d_in[11];
    const float* beta2  = (const float*)d_in[12];
    float* out = (float*)d_out;

    float *attn, *hbuf, *f2;
    fp16 *x16, *WqTh, *WqTl, *WoTh, *WoTl, *W1Th, *W1Tl, *W2Th, *W2Tl;
    fp16 *q16, *val16, *h16, *f116;
    cudaGetSymbolAddress((void**)&attn, g_attn);
    cudaGetSymbolAddress((void**)&hbuf, g_hf);
    cudaGetSymbolAddress((void**)&f2,   g_f2);
    cudaGetSymbolAddress((void**)&x16, g_x16);
    cudaGetSymbolAddress((void**)&WqTh, g_WqT_h); cudaGetSymbolAddress((void**)&WqTl, g_WqT_l);
    cudaGetSymbolAddress((void**)&WoTh, g_WoT_h); cudaGetSymbolAddress((void**)&WoTl, g_WoT_l);
    cudaGetSymbolAddress((void**)&W1Th, g_W1T_h); cudaGetSymbolAddress((void**)&W1Tl, g_W1T_l);
    cudaGetSymbolAddress((void**)&W2Th, g_W2T_h); cudaGetSymbolAddress((void**)&W2Tl, g_W2T_l);
    cudaGetSymbolAddress((void**)&q16, g_qkv16);
    cudaGetSymbolAddress((void**)&val16, g_vals16);
    cudaGetSymbolAddress((void**)&h16, g_h16);
    cudaGetSymbolAddress((void**)&f116, g_f116);

    const int SM128 = 2 * (10240 + 2 * 128 * 80);   // 61440
    const int SMFL  = 18432 + 2 * 36864;            // 92160
    cudaFuncSetAttribute(mm_gemm<128,1,false,true>, cudaFuncAttributeMaxDynamicSharedMemorySize, SM128);
    cudaFuncSetAttribute(mm_gemm<128,2,false,true>, cudaFuncAttributeMaxDynamicSharedMemorySize, SM128);
    cudaFuncSetAttribute(mm_gemm<128,3,true,false>, cudaFuncAttributeMaxDynamicSharedMemorySize, SM128);
    cudaFuncSetAttribute(flash_kernel, cudaFuncAttributeMaxDynamicSharedMemorySize, SMFL);

    const dim3 blk(256), gb(256);

    // 0) prep: weight transpose+split (fp16 hi/lo), x -> fp16
    tsplit_kernel<<<dim3(QKVW/32, DMODEL/32), blk>>>(W_qkv, WqTh, WqTl, DMODEL, QKVW);
    tsplit_kernel<<<dim3(DMODEL/32, DMODEL/32), blk>>>(W_o, WoTh, WoTl, DMODEL, DMODEL);
    tsplit_kernel<<<dim3(FFN/32, DMODEL/32), blk>>>(W1, W1Th, W1Tl, DMODEL, FFN);
    tsplit_kernel<<<dim3(DMODEL/32, FFN/32), blk>>>(W2, W2Th, W2Tl, FFN, DMODEL);
    tohalf_kernel<<<NTOK * DMODEL / 1024, blk>>>(x, x16, NTOK * DMODEL);

    // 1) qkv = x @ Wqkv + b -> fp16
    mm_gemm<128,1,false,true><<<dim3(QKVW/128, NTOK/128, 1), gb, SM128>>>(
        x16, WqTh, WqTl, nullptr, q16, b_qkv, nullptr,
        DMODEL, DMODEL, DMODEL, QKVW, 0, 1.0f);

    // 2) fused flash attention -> vals fp16 [tok][DMODEL]
    flash_kernel<<<dim3(SEQ/128, BATCH*NHEADS), gb, SMFL>>>(q16, val16);

    // 3) attn = vals @ Wo + b + x (residual), fp32
    mm_gemm<128,3,true,false><<<dim3(DMODEL/128, NTOK/128, 1), gb, SM128>>>(
        val16, WoTh, WoTl, attn, nullptr, b_o, x,
        DMODEL, DMODEL, DMODEL, DMODEL, DMODEL, 1.0f);

    // 4) h = LN1(attn): fp32 + fp16
    ln_kernel<<<NTOK, blk>>>(attn, gamma1, beta1, hbuf, h16);

    // 5) f1 = relu(h @ W1 + b1) -> fp16
    mm_gemm<128,2,false,true><<<dim3(FFN/128, NTOK/128, 1), gb, SM128>>>(
        h16, W1Th, W1Tl, nullptr, f116, b1, nullptr,
        DMODEL, DMODEL, DMODEL, FFN, 0, 1.0f);

    // 6) f2 = f1 @ W2 + b2 + h (residual), fp32
    mm_gemm<128,3,true,false><<<dim3(DMODEL/128, NTOK/128, 1), gb, SM128>>>(
        f116, W2Th, W2Tl, f2, nullptr, b2, hbuf,
        FFN, FFN, FFN, DMODEL, DMODEL, 1.0f);

    // 7) out = LN2(f2)
    ln_kernel<<<NTOK, blk>>>(f2, gamma2, beta2, out, nullptr);
}